// round 10
// baseline (speedup 1.0000x reference)
#include <cuda_runtime.h>
#include <cuda_fp16.h>
#include <cstdint>

#define NN 2048
#define DM 1024
#define NH 16
#define DK 64
#define LN_EPS 1e-5f
#define QKS 36   // u32 row stride for packed Q/K (32 pairs + 4 pad)

// Scratch (device globals)
__device__ uint32_t g_Xq8h[(size_t)NN * 256];          // int8 quads, hi
__device__ uint32_t g_Xq8l[(size_t)NN * 256];          // int8 quads, lo
__device__ uint32_t g_Wq8h[(size_t)NH * 192 * 256];    // int8 quads, hi ([h][sec*64+n][kq])
__device__ uint32_t g_Wq8l[(size_t)NH * 192 * 256];
__device__ uint32_t g_Wo[(size_t)DM * 512];            // single fp16 pairs
__device__ uint32_t g_Qh[(size_t)NH * NN * QKS];
__device__ uint32_t g_Ql[(size_t)NH * NN * QKS];
__device__ uint32_t g_Kh[(size_t)NH * NN * QKS];       // single fp16
__device__ uint32_t g_Vt[(size_t)NH * DK * (NN / 2)];  // fp16 [h][dk][keypair]
__device__ uint32_t g_Ch[(size_t)NN * 512];
__device__ uint32_t g_Cl[(size_t)NN * 512];
__device__ float    g_pre[(size_t)NN * DM];
__device__ uint32_t g_scaleBits[2];                    // [0]=max|x|, [1]=max|wqkv| (fp32 bits)

// ---------------------------------------------------------------------------
// helpers
// ---------------------------------------------------------------------------
__device__ __forceinline__ uint32_t pack2h(float e0, float e1) {  // f16x2: e0 low
    uint32_t r;
    asm("cvt.rn.f16x2.f32 %0, %1, %2;" : "=r"(r) : "f"(e1), "f"(e0));
    return r;
}
__device__ __forceinline__ uint16_t f16bits(float v) {
    uint16_t u;
    asm("cvt.rn.f16.f32 %0, %1;" : "=h"(u) : "f"(v));
    return u;
}
__device__ __forceinline__ void split2h(float x0, float x1, uint32_t& hi, uint32_t& lo) {
    __half2 h = __floats2half2_rn(x0, x1);
    float2 hf = __half22float2(h);
    __half2 l = __floats2half2_rn(x0 - hf.x, x1 - hf.y);
    hi = *(uint32_t*)&h;
    lo = *(uint32_t*)&l;
}
__device__ __forceinline__ void mma_f16(float* c, const uint32_t* a, const uint32_t* b) {
    asm("mma.sync.aligned.m16n8k16.row.col.f32.f16.f16.f32 "
        "{%0,%1,%2,%3}, {%4,%5,%6,%7}, {%8,%9}, {%0,%1,%2,%3};\n"
        : "+f"(c[0]), "+f"(c[1]), "+f"(c[2]), "+f"(c[3])
        : "r"(a[0]), "r"(a[1]), "r"(a[2]), "r"(a[3]), "r"(b[0]), "r"(b[1]));
}
__device__ __forceinline__ void mma_s8(int* c, const uint32_t* a, const uint32_t* b) {
    asm("mma.sync.aligned.m16n8k32.row.col.s32.s8.s8.s32 "
        "{%0,%1,%2,%3}, {%4,%5,%6,%7}, {%8,%9}, {%0,%1,%2,%3};\n"
        : "+r"(c[0]), "+r"(c[1]), "+r"(c[2]), "+r"(c[3])
        : "r"(a[0]), "r"(a[1]), "r"(a[2]), "r"(a[3]), "r"(b[0]), "r"(b[1]));
}
__device__ __forceinline__ void ldsm_x4(uint32_t* r, const uint32_t* p) {
    uint32_t addr = (uint32_t)__cvta_generic_to_shared(p);
    asm volatile("ldmatrix.sync.aligned.m8n8.x4.shared.b16 {%0,%1,%2,%3}, [%4];"
        : "=r"(r[0]), "=r"(r[1]), "=r"(r[2]), "=r"(r[3]) : "r"(addr));
}
#define CPA16(sptr, gptr) do {                                                 \
    uint32_t _s = (uint32_t)__cvta_generic_to_shared(sptr);                    \
    asm volatile("cp.async.cg.shared.global [%0], [%1], 16;" :: "r"(_s), "l"(gptr)); \
} while (0)
#define CP_COMMIT() asm volatile("cp.async.commit_group;")
#define CP_WAIT(n)  asm volatile("cp.async.wait_group %0;" :: "n"(n))

// int8 quantization: x ~= (s/127) * (ah + al/256)
__device__ __forceinline__ void quant2(float x, float inv, int& ah, int& al) {
    float q = x * inv;                       // |q| <= 127
    float h = rintf(q);
    ah = (int)h;
    int l = (int)rintf((q - h) * 256.0f);    // [-128, 128]
    al = max(-127, min(127, l));
}
__device__ __forceinline__ uint32_t packq(int a0, int a1, int a2, int a3) {
    return (uint32_t)(a0 & 0xFF) | ((uint32_t)(a1 & 0xFF) << 8) |
           ((uint32_t)(a2 & 0xFF) << 16) | ((uint32_t)(a3 & 0xFF) << 24);
}

// ---------------------------------------------------------------------------
// scale pass
// ---------------------------------------------------------------------------
__global__ void zero_scales_kernel(uint32_t* sb) {
    sb[0] = 0; sb[1] = 0;
}
__global__ void __launch_bounds__(256) maxabs_kernel(const float* __restrict__ p,
                                                     int n, uint32_t* __restrict__ out)
{
    float m = 0.f;
    for (int i = blockIdx.x * 256 + threadIdx.x; i < n; i += gridDim.x * 256)
        m = fmaxf(m, fabsf(p[i]));
    #pragma unroll
    for (int d = 16; d >= 1; d >>= 1)
        m = fmaxf(m, __shfl_xor_sync(0xffffffffu, m, d));
    __shared__ float sm[8];
    int warp = threadIdx.x >> 5, lane = threadIdx.x & 31;
    if (lane == 0) sm[warp] = m;
    __syncthreads();
    if (threadIdx.x == 0) {
        float t = 0.f;
        #pragma unroll
        for (int i = 0; i < 8; i++) t = fmaxf(t, sm[i]);
        atomicMax(out, __float_as_uint(t));   // positive floats: bit order = value order
    }
}

// ---------------------------------------------------------------------------
// conversion kernels
// ---------------------------------------------------------------------------
__global__ void __launch_bounds__(256) conv_x_q8_kernel(const float* __restrict__ x,
                                                        uint32_t* __restrict__ Xh,
                                                        uint32_t* __restrict__ Xl)
{
    const int r = blockIdx.x, t = threadIdx.x;
    const float sx = fmaxf(__uint_as_float(g_scaleBits[0]), 1e-30f);
    const float inv = 127.0f / sx;
    float4 v = ((const float4*)x)[r * 256 + t];
    int h0, l0, h1, l1, h2, l2, h3, l3;
    quant2(v.x, inv, h0, l0);
    quant2(v.y, inv, h1, l1);
    quant2(v.z, inv, h2, l2);
    quant2(v.w, inv, h3, l3);
    Xh[(size_t)r * 256 + t] = packq(h0, h1, h2, h3);
    Xl[(size_t)r * 256 + t] = packq(l0, l1, l2, l3);
}

// wq/wk/wv -> int8 quads, [h][sec*64+n][kq], row stride 256 u32
__global__ void __launch_bounds__(256) conv_wqkv_q8_kernel(const float* __restrict__ wq,
                                                           const float* __restrict__ wk,
                                                           const float* __restrict__ wv,
                                                           uint32_t* __restrict__ dstH,
                                                           uint32_t* __restrict__ dstL)
{
    __shared__ float sw[64][65];
    const int k0 = blockIdx.x * 64;
    const int z  = blockIdx.z;
    const int sec = z >> 4, h = z & 15;
    const int t  = threadIdx.x;
    const float* s = (sec == 0 ? wq : sec == 1 ? wk : wv) + (size_t)h * DM * DK;
    const float swm = fmaxf(__uint_as_float(g_scaleBits[1]), 1e-30f);
    const float inv = 127.0f / swm;

    #pragma unroll
    for (int i = 0; i < 16; i++) {
        int idx = i * 256 + t;
        int row = idx >> 6, col = idx & 63;
        sw[row][col] = s[(size_t)(k0 + row) * DK + col];
    }
    __syncthreads();
    #pragma unroll
    for (int i = 0; i < 4; i++) {
        int idx = i * 256 + t;              // 64 n x 16 kq
        int n = idx >> 4, kq = idx & 15;
        int h0, l0, h1, l1, h2, l2, h3, l3;
        quant2(sw[4 * kq + 0][n], inv, h0, l0);
        quant2(sw[4 * kq + 1][n], inv, h1, l1);
        quant2(sw[4 * kq + 2][n], inv, h2, l2);
        quant2(sw[4 * kq + 3][n], inv, h3, l3);
        size_t o = (size_t)h * (192 * 256) + (size_t)(sec * 64 + n) * 256 + k0 / 4 + kq;
        dstH[o] = packq(h0, h1, h2, h3);
        dstL[o] = packq(l0, l1, l2, l3);
    }
}

__global__ void __launch_bounds__(256) conv_wo_kernel(const float* __restrict__ src,
                                                      uint32_t* __restrict__ dst)
{
    __shared__ float sw[64][65];
    const int k0 = blockIdx.x * 64;
    const int n0 = blockIdx.y * 64;
    const int t  = threadIdx.x;

    #pragma unroll
    for (int i = 0; i < 16; i++) {
        int idx = i * 256 + t;
        int row = idx >> 6, col = idx & 63;
        sw[row][col] = src[(size_t)(k0 + row) * DM + n0 + col];
    }
    __syncthreads();
    #pragma unroll
    for (int i = 0; i < 8; i++) {
        int idx = i * 256 + t;
        int n = idx >> 5, kp = idx & 31;
        size_t o = (size_t)(n0 + n) * 512 + k0 / 2 + kp;
        dst[o] = pack2h(sw[2 * kp][n], sw[2 * kp + 1][n]);
    }
}

// ---------------------------------------------------------------------------
// int8 QKV GEMM: CTA = (row-tile 128, head, section), 64 cols.
// 3-term IMMA k32 (hh -> P1; lh+hl -> P2). k-chunk = 64 (16 u32/row).
// Stage = Ah(2560) + Al(2560) + Bh(1280) + Bl(1280) = 7680 u32; 2 stages = 61440 B.
// ---------------------------------------------------------------------------
#define Q8_STAGE_U32 7680
#define Q8_SMEM (2 * Q8_STAGE_U32 * 4)

__device__ __forceinline__ void q8_stage_load(uint32_t* st,
                                              const uint32_t* Ahg, const uint32_t* Alg,
                                              const uint32_t* Bhg, const uint32_t* Blg,
                                              int kc16, int tid)
{
    #pragma unroll
    for (int i = 0; i < 2; i++) {
        int idx = tid + i * 256;               // 0..511 (128 rows x 4 groups)
        int row = idx >> 2, sg = (idx & 3) * 4;
        CPA16(st + row * 20 + sg,        Ahg + (size_t)row * 256 + kc16 + sg);
        CPA16(st + 2560 + row * 20 + sg, Alg + (size_t)row * 256 + kc16 + sg);
    }
    {
        int row = tid >> 2, sg = (tid & 3) * 4;  // rows 0..63
        CPA16(st + 5120 + row * 20 + sg, Bhg + (size_t)row * 256 + kc16 + sg);
        CPA16(st + 6400 + row * 20 + sg, Blg + (size_t)row * 256 + kc16 + sg);
    }
}

__global__ void __launch_bounds__(256, 2) qkv_q8_kernel(const uint32_t* __restrict__ Xh,
                                                        const uint32_t* __restrict__ Xl,
                                                        const uint32_t* __restrict__ Wh,
                                                        const uint32_t* __restrict__ Wl,
                                                        const float* __restrict__ qb,
                                                        const float* __restrict__ kb,
                                                        const float* __restrict__ vb,
                                                        uint32_t* __restrict__ oQh,
                                                        uint32_t* __restrict__ oQl,
                                                        uint32_t* __restrict__ oKh,
                                                        uint32_t* __restrict__ oVt)
{
    extern __shared__ uint32_t sm[];
    const int m0  = blockIdx.x * 128;
    const int h   = blockIdx.y;
    const int sec = blockIdx.z;
    const int tid = threadIdx.x;
    const int wid = tid >> 5, lane = tid & 31, g = lane >> 2, t = lane & 3;
    const int lrow = lane & 7;
    const int aoff = (wid * 16 + lrow + ((lane >> 3) & 1) * 8) * 20 + (lane >> 4) * 4;
    const int boff = (lrow + ((lane >> 4) & 1) * 8) * 20 + ((lane >> 3) & 1) * 4;

    const uint32_t* Ahg = Xh + (size_t)m0 * 256;
    const uint32_t* Alg = Xl + (size_t)m0 * 256;
    const uint32_t* Bhg = Wh + ((size_t)h * 192 + sec * 64) * 256;
    const uint32_t* Blg = Wl + ((size_t)h * 192 + sec * 64) * 256;

    int accH[8][4] = {};
    int accM[8][4] = {};

    q8_stage_load(sm, Ahg, Alg, Bhg, Blg, 0, tid);
    CP_COMMIT();

    for (int c = 0; c < 16; c++) {
        if (c < 15) {
            q8_stage_load(sm + ((c + 1) & 1) * Q8_STAGE_U32,
                          Ahg, Alg, Bhg, Blg, (c + 1) * 16, tid);
            CP_COMMIT();
            CP_WAIT(1);
        } else {
            CP_WAIT(0);
        }
        __syncthreads();

        const uint32_t* p  = sm + (c & 1) * Q8_STAGE_U32;
        const uint32_t* Ah = p;
        const uint32_t* Al = p + 2560;
        const uint32_t* Bh = p + 5120;
        const uint32_t* Bl = p + 6400;

        #pragma unroll
        for (int ks = 0; ks < 2; ks++) {          // two k32 halves of the k64 chunk
            uint32_t ah[4], al[4];
            ldsm_x4(ah, Ah + aoff + ks * 8);
            ldsm_x4(al, Al + aoff + ks * 8);
            // term hh -> P1
            #pragma unroll
            for (int nbp = 0; nbp < 4; nbp++) {
                uint32_t bh[4];
                ldsm_x4(bh, Bh + boff + nbp * 320 + ks * 8);
                mma_s8(accH[2 * nbp],     ah, bh);
                mma_s8(accH[2 * nbp + 1], ah, bh + 2);
            }
            // term lh -> P2
            #pragma unroll
            for (int nbp = 0; nbp < 4; nbp++) {
                uint32_t bh[4];
                ldsm_x4(bh, Bh + boff + nbp * 320 + ks * 8);
                mma_s8(accM[2 * nbp],     al, bh);
                mma_s8(accM[2 * nbp + 1], al, bh + 2);
            }
            // term hl -> P2
            #pragma unroll
            for (int nbp = 0; nbp < 4; nbp++) {
                uint32_t bl[4];
                ldsm_x4(bl, Bl + boff + nbp * 320 + ks * 8);
                mma_s8(accM[2 * nbp],     ah, bl);
                mma_s8(accM[2 * nbp + 1], ah, bl + 2);
            }
        }
        __syncthreads();
    }

    // rescale: val = (sx/127)*(sw/127)*(P1 + P2/256)
    const float sx = fmaxf(__uint_as_float(g_scaleBits[0]), 1e-30f);
    const float sw = fmaxf(__uint_as_float(g_scaleBits[1]), 1e-30f);
    const float sprod = (sx * sw) * (1.0f / 16129.0f);

    float acc[8][4];
    #pragma unroll
    for (int nb = 0; nb < 8; nb++)
        #pragma unroll
        for (int j = 0; j < 4; j++)
            acc[nb][j] = sprod * ((float)accH[nb][j] + (float)accM[nb][j] * 0.00390625f);

    const int r = wid * 16 + g;
    const int grow = m0 + r;

    if (sec == 0) {
        #pragma unroll
        for (int nb = 0; nb < 8; nb++) {
            int col = nb * 8 + 2 * t;
            float b0 = qb[h * DK + col], b1 = qb[h * DK + col + 1];
            uint32_t h0, l0, h1, l1;
            split2h((acc[nb][0] + b0) * 0.125f, (acc[nb][1] + b1) * 0.125f, h0, l0);
            split2h((acc[nb][2] + b0) * 0.125f, (acc[nb][3] + b1) * 0.125f, h1, l1);
            size_t base = ((size_t)h * NN + grow) * QKS + nb * 4 + t;
            oQh[base] = h0;            oQl[base] = l0;
            oQh[base + 8 * QKS] = h1;  oQl[base + 8 * QKS] = l1;
        }
    } else if (sec == 1) {
        #pragma unroll
        for (int nb = 0; nb < 8; nb++) {
            int col = nb * 8 + 2 * t;
            float b0 = kb[h * DK + col], b1 = kb[h * DK + col + 1];
            size_t base = ((size_t)h * NN + grow) * QKS + nb * 4 + t;
            oKh[base]           = pack2h(acc[nb][0] + b0, acc[nb][1] + b1);
            oKh[base + 8 * QKS] = pack2h(acc[nb][2] + b0, acc[nb][3] + b1);
        }
    } else {
        uint16_t* Vs16 = (uint16_t*)sm;   // [64 dk][132 fp16]
        #pragma unroll
        for (int nb = 0; nb < 8; nb++) {
            int col = nb * 8 + 2 * t;
            float b0 = vb[h * DK + col], b1 = vb[h * DK + col + 1];
            Vs16[(col)     * 132 + r]     = f16bits(acc[nb][0] + b0);
            Vs16[(col + 1) * 132 + r]     = f16bits(acc[nb][1] + b1);
            Vs16[(col)     * 132 + r + 8] = f16bits(acc[nb][2] + b0);
            Vs16[(col + 1) * 132 + r + 8] = f16bits(acc[nb][3] + b1);
        }
        __syncthreads();
        #pragma unroll
        for (int i = 0; i < 16; i++) {
            int idx = tid + i * 256;
            int dk = idx >> 6, cc = idx & 63;
            oVt[((size_t)h * DK + dk) * (NN / 2) + m0 / 2 + cc] = sm[dk * 66 + cc];
        }
    }
}

// ---------------------------------------------------------------------------
// fp16 GEMM machinery (outproj): 2-term A split, B single — unchanged round 9.
// ---------------------------------------------------------------------------
#define G_STAGE_U32 6400
#define G_SMEM (2 * G_STAGE_U32 * 4)

__device__ __forceinline__ void gemm_stage_load(uint32_t* st,
                                                const uint32_t* Ahg, const uint32_t* Alg,
                                                const uint32_t* Bg,
                                                int kc16, int tid)
{
    #pragma unroll
    for (int i = 0; i < 2; i++) {
        int idx = tid + i * 256;
        int row = idx >> 2, sg = (idx & 3) * 4;
        CPA16(st + row * 20 + sg,        Ahg + (size_t)row * 512 + kc16 + sg);
        CPA16(st + 2560 + row * 20 + sg, Alg + (size_t)row * 512 + kc16 + sg);
    }
    {
        int row = tid >> 2, sg = (tid & 3) * 4;
        CPA16(st + 5120 + row * 20 + sg, Bg + (size_t)row * 512 + kc16 + sg);
    }
}

__global__ void __launch_bounds__(256, 3) outproj_kernel(const uint32_t* __restrict__ Ahg,
                                                         const uint32_t* __restrict__ Alg,
                                                         const uint32_t* __restrict__ Bg,
                                                         const float* __restrict__ x,
                                                         const float* __restrict__ ob,
                                                         float* __restrict__ out)
{
    extern __shared__ uint32_t sm[];
    const int m0 = blockIdx.x * 128;
    const int c0 = blockIdx.y * 64;
    const int tid = threadIdx.x;
    const int wid = tid >> 5, lane = tid & 31, g = lane >> 2, t = lane & 3;
    const int lrow = lane & 7;
    const int aoff = (wid * 16 + lrow + ((lane >> 3) & 1) * 8) * 20 + (lane >> 4) * 4;
    const int boff = (lrow + ((lane >> 4) & 1) * 8) * 20 + ((lane >> 3) & 1) * 4;

    float acc[8][4] = {};

    gemm_stage_load(sm, Ahg + (size_t)m0 * 512, Alg + (size_t)m0 * 512,
                    Bg + (size_t)c0 * 512, 0, tid);
    CP_COMMIT();

    for (int c = 0; c < 32; c++) {
        if (c < 31) {
            gemm_stage_load(sm + ((c + 1) & 1) * G_STAGE_U32,
                            Ahg + (size_t)m0 * 512, Alg + (size_t)m0 * 512,
                            Bg + (size_t)c0 * 512, (c + 1) * 16, tid);
            CP_COMMIT();
            CP_WAIT(1);
        } else {
            CP_WAIT(0);
        }
        __syncthreads();

        const uint32_t* p  = sm + (c & 1) * G_STAGE_U32;
        const uint32_t* Ah = p;
        const uint32_t* Al = p + 2560;
        const uint32_t* Bs = p + 5120;

        #pragma unroll
        for (int ks = 0; ks < 2; ks++) {
            uint32_t ah[4], al[4];
            ldsm_x4(ah, Ah + aoff + ks * 8);
            ldsm_x4(al, Al + aoff + ks * 8);
            #pragma unroll
            for (int nbp = 0; nbp < 4; nbp++) {
                uint32_t b[4];
                ldsm_x4(b, Bs + boff + nbp * 320 + ks * 8);
                mma_f16(acc[2 * nbp],     ah, b);
                mma_f16(acc[2 * nbp + 1], ah, b + 2);
            }
            #pragma unroll
            for (int nbp = 0; nbp < 4; nbp++) {
                uint32_t b[4];
                ldsm_x4(b, Bs + boff + nbp * 320 + ks * 8);
                mma_f16(acc[2 * nbp],     al, b);
                mma_f16(acc[2 * nbp + 1], al, b + 2);
            }
        }
        __syncthreads();
    }

    const int r0 = m0 + wid * 16 + g;
    #pragma unroll
    for (int nb = 0; nb < 8; nb++) {
        int col = c0 + nb * 8 + 2 * t;
        float b0 = ob[col], b1 = ob[col + 1];
        const float* xr0 = &x[(size_t)r0 * DM + col];
        const float* xr1 = &x[(size_t)(r0 + 8) * DM + col];
        float2 v0 = make_float2(acc[nb][0] + b0 + xr0[0], acc[nb][1] + b1 + xr0[1]);
        float2 v1 = make_float2(acc[nb][2] + b0 + xr1[0], acc[nb][3] + b1 + xr1[1]);
        *(float2*)&out[(size_t)r0 * DM + col]       = v0;
        *(float2*)&out[(size_t)(r0 + 8) * DM + col] = v1;
    }
}

// ---------------------------------------------------------------------------
// Flash attention: fp16 QK (2-term, Q split / K single) + fp16 PV — unchanged.
// ---------------------------------------------------------------------------
#define ATTN_BUF_U32 (2 * 64 * 36)
#define ATTN_SMEM_BYTES (2 * ATTN_BUF_U32 * 4)

__device__ __forceinline__ void attn_stage(uint32_t* dst, const uint32_t* Kh,
                                           const uint32_t* Vt,
                                           int h, int t0, int tid)
{
    const uint32_t* sKh = Kh + ((size_t)h * NN + t0) * QKS;
    const uint32_t* sVt = Vt + (size_t)h * DK * (NN / 2) + t0 / 2;
    for (int idx = tid; idx < 1088; idx += 256) {
        if (idx < 576) {
            CPA16(dst + idx * 4, sKh + idx * 4);
        } else {
            int j = idx - 576;
            int dk = j >> 3, c = (j & 7) * 4;
            CPA16(dst + 2304 + dk * 36 + c, sVt + (size_t)dk * (NN / 2) + c);
        }
    }
}

__global__ void __launch_bounds__(256, 2) attn_kernel(const uint32_t* __restrict__ Qh,
                                                      const uint32_t* __restrict__ Ql,
                                                      const uint32_t* __restrict__ Kh,
                                                      const uint32_t* __restrict__ Vt,
                                                      uint32_t* __restrict__ Ch,
                                                      uint32_t* __restrict__ Cl)
{
    extern __shared__ uint32_t sm[];
    const int h  = blockIdx.y;
    const int q0 = blockIdx.x * 128;
    const int tid = threadIdx.x;
    const int wid = tid >> 5, lane = tid & 31, g = lane >> 2, t = lane & 3;
    const int lrow = lane & 7;
    const int boff = (lrow + ((lane >> 4) & 1) * 8) * 36 + ((lane >> 3) & 1) * 4;

    attn_stage(sm, Kh, Vt, h, 0, tid);
    CP_COMMIT();

    uint32_t ah[4][4], al[4][4];
    {
        const uint32_t* qh = Qh + ((size_t)h * NN + q0 + wid * 16 + g) * QKS;
        const uint32_t* ql = Ql + ((size_t)h * NN + q0 + wid * 16 + g) * QKS;
        #pragma unroll
        for (int ks = 0; ks < 4; ks++) {
            ah[ks][0] = qh[ks * 8 + t];       ah[ks][1] = qh[8 * QKS + ks * 8 + t];
            ah[ks][2] = qh[ks * 8 + t + 4];   ah[ks][3] = qh[8 * QKS + ks * 8 + t + 4];
            al[ks][0] = ql[ks * 8 + t];       al[ks][1] = ql[8 * QKS + ks * 8 + t];
            al[ks][2] = ql[ks * 8 + t + 4];   al[ks][3] = ql[8 * QKS + ks * 8 + t + 4];
        }
    }

    float o[8][4] = {};
    float m0 = -1e30f, m1 = -1e30f, l0 = 0.f, l1 = 0.f;

    for (int tt = 0; tt < NN / 64; tt++) {
        uint32_t* buf = sm + (tt & 1) * ATTN_BUF_U32;
        if (tt + 1 < NN / 64) {
            attn_stage(sm + ((tt + 1) & 1) * ATTN_BUF_U32, Kh, Vt, h, (tt + 1) * 64, tid);
            CP_COMMIT();
            CP_WAIT(1);
        } else {
            CP_WAIT(0);
        }
        __syncthreads();

        const uint32_t* kh = buf;
        const uint32_t* vs = buf + 2304;

        float s[8][4] = {};
        #pragma unroll
        for (int ks = 0; ks < 4; ks++) {
            #pragma unroll
            for (int nbp = 0; nbp < 4; nbp++) {
                uint32_t b[4];
                ldsm_x4(b, kh + boff + nbp * 576 + ks * 8);
                mma_f16(s[2 * nbp],     ah[ks], b);
                mma_f16(s[2 * nbp + 1], ah[ks], b + 2);
            }
            #pragma unroll
            for (int nbp = 0; nbp < 4; nbp++) {
                uint32_t b[4];
                ldsm_x4(b, kh + boff + nbp * 576 + ks * 8);
                mma_f16(s[2 * nbp],     al[ks], b);
                mma_f16(s[2 * nbp + 1], al[ks], b + 2);
            }
        }

        float mx0 = -1e30f, mx1 = -1e30f;
        #pragma unroll
        for (int nb = 0; nb < 8; nb++) {
            mx0 = fmaxf(mx0, fmaxf(s[nb][0], s[nb][1]));
            mx1 = fmaxf(mx1, fmaxf(s[nb][2], s[nb][3]));
        }
        mx0 = fmaxf(mx0, __shfl_xor_sync(0xffffffffu, mx0, 1));
        mx0 = fmaxf(mx0, __shfl_xor_sync(0xffffffffu, mx0, 2));
        mx1 = fmaxf(mx1, __shfl_xor_sync(0xffffffffu, mx1, 1));
        mx1 = fmaxf(mx1, __shfl_xor_sync(0xffffffffu, mx1, 2));

        float nm0 = fmaxf(m0, mx0), nm1 = fmaxf(m1, mx1);
        float sc0 = __expf(m0 - nm0), sc1 = __expf(m1 - nm1);
        float sum0 = 0.f, sum1 = 0.f;
        #pragma unroll
        for (int nb = 0; nb < 8; nb++) {
            s[nb][0] = __expf(s[nb][0] - nm0);
            s[nb][1] = __expf(s[nb][1] - nm0);
            s[nb][2] = __expf(s[nb][2] - nm1);
            s[nb][3] = __expf(s[nb][3] - nm1);
            sum0 += s[nb][0] + s[nb][1];
            sum1 += s[nb][2] + s[nb][3];
        }
        sum0 += __shfl_xor_sync(0xffffffffu, sum0, 1);
        sum0 += __shfl_xor_sync(0xffffffffu, sum0, 2);
        sum1 += __shfl_xor_sync(0xffffffffu, sum1, 1);
        sum1 += __shfl_xor_sync(0xffffffffu, sum1, 2);
        l0 = l0 * sc0 + sum0;  m0 = nm0;
        l1 = l1 * sc1 + sum1;  m1 = nm1;
        #pragma unroll
        for (int nb = 0; nb < 8; nb++) {
            o[nb][0] *= sc0; o[nb][1] *= sc0;
            o[nb][2] *= sc1; o[nb][3] *= sc1;
        }

        #pragma unroll
        for (int kp = 0; kp < 4; kp++) {
            uint32_t ap[4];
            ap[0] = pack2h(s[2 * kp][0],     s[2 * kp][1]);
            ap[1] = pack2h(s[2 * kp][2],     s[2 * kp][3]);
            ap[2] = pack2h(s[2 * kp + 1][0], s[2 * kp + 1][1]);
            ap[3] = pack2h(s[2 * kp + 1][2], s[2 * kp + 1][3]);
            #pragma unroll
            for (int nbp = 0; nbp < 4; nbp++) {
                uint32_t b[4];
                ldsm_x4(b, vs + boff + nbp * 576 + kp * 8);
                mma_f16(o[2 * nbp],     ap, b);
                mma_f16(o[2 * nbp + 1], ap, b + 2);
            }
        }
        __syncthreads();
    }

    const float inv0 = 1.0f / l0, inv1 = 1.0f / l1;
    const int r0 = q0 + wid * 16 + g;
    #pragma unroll
    for (int nb = 0; nb < 8; nb++) {
        int cpi = h * 32 + nb * 4 + t;
        uint32_t h0, lo0, h1, lo1;
        split2h(o[nb][0] * inv0, o[nb][1] * inv0, h0, lo0);
        split2h(o[nb][2] * inv1, o[nb][3] * inv1, h1, lo1);
        Ch[(size_t)r0 * 512 + cpi]       = h0;  Cl[(size_t)r0 * 512 + cpi]       = lo0;
        Ch[(size_t)(r0 + 8) * 512 + cpi] = h1;  Cl[(size_t)(r0 + 8) * 512 + cpi] = lo1;
    }
}

// ---------------------------------------------------------------------------
// LayerNorm, one block per row
// ---------------------------------------------------------------------------
__global__ void __launch_bounds__(256) ln_kernel(const float* __restrict__ pre,
                                                 const float* __restrict__ alpha,
                                                 const float* __restrict__ beta,
                                                 float* __restrict__ out)
{
    const int row = blockIdx.x;
    const int tid = threadIdx.x;
    const float4 v = ((const float4*)(pre + (size_t)row * DM))[tid];

    float sum = v.x + v.y + v.z + v.w;
    float sq  = v.x * v.x + v.y * v.y + v.z * v.z + v.w * v.w;

    #pragma unroll
    for (int d = 16; d >= 1; d >>= 1) {
        sum += __shfl_xor_sync(0xffffffffu, sum, d);
        sq  += __shfl_xor_sync(0xffffffffu, sq,  d);
    }

    __shared__ float ssum[8], ssq[8];
    __shared__ float s_mu, s_rstd;
    int warp = tid >> 5, lane = tid & 31;
    if (lane == 0) { ssum[warp] = sum; ssq[warp] = sq; }
    __syncthreads();
    if (tid == 0) {
        float ts = 0.f, tq = 0.f;
        #pragma unroll
        for (int i = 0; i < 8; i++) { ts += ssum[i]; tq += ssq[i]; }
        float mu  = ts * (1.0f / DM);
        float var = tq * (1.0f / DM) - mu * mu;
        s_mu = mu;
        s_rstd = rsqrtf(var + LN_EPS);
    }
    __syncthreads();

    const float mu = s_mu, rstd = s_rstd;
    const float4 a4 = ((const float4*)alpha)[tid];
    const float4 b4 = ((const float4*)beta)[tid];
    float4 r;
    r.x = a4.x * (v.x - mu) * rstd + b4.x;
    r.y = a4.y * (v.y - mu) * rstd + b4.y;
    r.z = a4.z * (v.z - mu) * rstd + b4.z;
    r.w = a4.w * (v.w - mu) * rstd + b4.w;
    ((float4*)(out + (size_t)row * DM))[tid] = r;
}

// ---------------------------------------------------------------------------
extern "C" void kernel_launch(void* const* d_in, const int* in_sizes, int n_in,
                              void* d_out, int out_size)
{
    const float* x     = (const float*)d_in[0];
    const float* wq    = (const float*)d_in[1];
    const float* qb    = (const float*)d_in[2];
    const float* wk    = (const float*)d_in[3];
    const float* kb    = (const float*)d_in[4];
    const float* wv    = (const float*)d_in[5];
    const float* vb    = (const float*)d_in[6];
    const float* wo    = (const float*)d_in[7];
    const float* ob    = (const float*)d_in[8];
    const float* alpha = (const float*)d_in[9];
    const float* beta  = (const float*)d_in[10];
    float* out = (float*)d_out;

    uint32_t *Xh, *Xl, *Wh, *Wl, *Wo;
    uint32_t *Qh, *Ql, *Kh, *Vt, *Ch, *Cl, *scaleBits;
    float *pre;
    cudaGetSymbolAddress((void**)&Xh,  g_Xq8h);
    cudaGetSymbolAddress((void**)&Xl,  g_Xq8l);
    cudaGetSymbolAddress((void**)&Wh,  g_Wq8h);
    cudaGetSymbolAddress((void**)&Wl,  g_Wq8l);
    cudaGetSymbolAddress((void**)&Wo,  g_Wo);
    cudaGetSymbolAddress((void**)&Qh,  g_Qh);
    cudaGetSymbolAddress((void**)&Ql,  g_Ql);
    cudaGetSymbolAddress((void**)&Kh,  g_Kh);
    cudaGetSymbolAddress((void**)&Vt,  g_Vt);
    cudaGetSymbolAddress((void**)&Ch,  g_Ch);
    cudaGetSymbolAddress((void**)&Cl,  g_Cl);
    cudaGetSymbolAddress((void**)&pre, g_pre);
    cudaGetSymbolAddress((void**)&scaleBits, g_scaleBits);

    cudaFuncSetAttribute(qkv_q8_kernel,
                         cudaFuncAttributeMaxDynamicSharedMemorySize, Q8_SMEM);
    cudaFuncSetAttribute(outproj_kernel,
                         cudaFuncAttributeMaxDynamicSharedMemorySize, G_SMEM);
    cudaFuncSetAttribute(attn_kernel,
                         cudaFuncAttributeMaxDynamicSharedMemorySize, ATTN_SMEM_BYTES);

    // scale pass
    zero_scales_kernel<<<1, 1>>>(scaleBits);
    maxabs_kernel<<<256, 256>>>(x,  NN * DM, scaleBits + 0);
    maxabs_kernel<<<256, 256>>>(wq, NH * DM * DK, scaleBits + 1);
    maxabs_kernel<<<256, 256>>>(wk, NH * DM * DK, scaleBits + 1);
    maxabs_kernel<<<256, 256>>>(wv, NH * DM * DK, scaleBits + 1);

    // conversions
    conv_x_q8_kernel<<<NN, 256>>>(x, Xh, Xl);
    conv_wqkv_q8_kernel<<<dim3(16, 1, 48), 256>>>(wq, wk, wv, Wh, Wl);
    conv_wo_kernel<<<dim3(16, 16, 1), 256>>>(wo, Wo);

    qkv_q8_kernel<<<dim3(NN / 128, NH, 3), 256, Q8_SMEM>>>(Xh, Xl, Wh, Wl,
                                                           qb, kb, vb,
                                                           Qh, Ql, Kh, Vt);

    attn_kernel<<<dim3(NN / 128, NH), 256, ATTN_SMEM_BYTES>>>(Qh, Ql, Kh, Vt, Ch, Cl);

    outproj_kernel<<<dim3(NN / 128, DM / 64), 256, G_SMEM>>>(Ch, Cl, Wo,
                                                             x, ob, pre);

    ln_kernel<<<NN, 256>>>(pre, alpha, beta, out);
}

// round 11
// speedup vs baseline: 2.0691x; 2.0691x over previous
#include <cuda_runtime.h>
#include <cuda_fp16.h>
#include <cstdint>

#define NN 2048
#define DM 1024
#define NH 16
#define DK 64
#define LN_EPS 1e-5f
#define QKS 36   // u32 row stride for packed Q/K (32 pairs + 4 pad)

// Scratch (device globals) — fp16 pair arrays (u32 = f16x2)
__device__ uint32_t g_Xh[(size_t)NN * 512];
__device__ uint32_t g_Xl[(size_t)NN * 512];
__device__ uint32_t g_Wq[(size_t)NH * 192 * 512];     // single fp16
__device__ uint32_t g_Wo[(size_t)DM * 512];           // single fp16
__device__ uint32_t g_Qh[(size_t)NH * NN * QKS];
__device__ uint32_t g_Ql[(size_t)NH * NN * QKS];
__device__ uint32_t g_Kh[(size_t)NH * NN * QKS];      // single fp16
__device__ uint32_t g_Vt[(size_t)NH * DK * (NN / 2)]; // fp16 [h][dk][keypair]
__device__ uint32_t g_Ch[(size_t)NN * 512];
__device__ uint32_t g_Cl[(size_t)NN * 512];
__device__ float    g_pre[(size_t)NN * DM];

// ---------------------------------------------------------------------------
// helpers
// ---------------------------------------------------------------------------
__device__ __forceinline__ uint32_t pack2h(float e0, float e1) {  // f16x2: e0 low
    uint32_t r;
    asm("cvt.rn.f16x2.f32 %0, %1, %2;" : "=r"(r) : "f"(e1), "f"(e0));
    return r;
}
__device__ __forceinline__ uint16_t f16bits(float v) {
    uint16_t u;
    asm("cvt.rn.f16.f32 %0, %1;" : "=h"(u) : "f"(v));
    return u;
}
// split pair (x0,x1) into hi-f16x2 + lo-f16x2 residual
__device__ __forceinline__ void split2h(float x0, float x1, uint32_t& hi, uint32_t& lo) {
    __half2 h = __floats2half2_rn(x0, x1);
    float2 hf = __half22float2(h);
    __half2 l = __floats2half2_rn(x0 - hf.x, x1 - hf.y);
    hi = *(uint32_t*)&h;
    lo = *(uint32_t*)&l;
}
__device__ __forceinline__ void mma_f16(float* c, const uint32_t* a, const uint32_t* b) {
    asm("mma.sync.aligned.m16n8k16.row.col.f32.f16.f16.f32 "
        "{%0,%1,%2,%3}, {%4,%5,%6,%7}, {%8,%9}, {%0,%1,%2,%3};\n"
        : "+f"(c[0]), "+f"(c[1]), "+f"(c[2]), "+f"(c[3])
        : "r"(a[0]), "r"(a[1]), "r"(a[2]), "r"(a[3]), "r"(b[0]), "r"(b[1]));
}
__device__ __forceinline__ void ldsm_x4(uint32_t* r, const uint32_t* p) {
    uint32_t addr = (uint32_t)__cvta_generic_to_shared(p);
    asm volatile("ldmatrix.sync.aligned.m8n8.x4.shared.b16 {%0,%1,%2,%3}, [%4];"
        : "=r"(r[0]), "=r"(r[1]), "=r"(r[2]), "=r"(r[3]) : "r"(addr));
}
#define CPA16(sptr, gptr) do {                                                 \
    uint32_t _s = (uint32_t)__cvta_generic_to_shared(sptr);                    \
    asm volatile("cp.async.cg.shared.global [%0], [%1], 16;" :: "r"(_s), "l"(gptr)); \
} while (0)
#define CP_COMMIT() asm volatile("cp.async.commit_group;")
#define CP_WAIT(n)  asm volatile("cp.async.wait_group %0;" :: "n"(n))

// ---------------------------------------------------------------------------
// conversion kernels
// ---------------------------------------------------------------------------
__global__ void __launch_bounds__(256) conv_x_kernel(const float* __restrict__ x,
                                                     uint32_t* __restrict__ Xh,
                                                     uint32_t* __restrict__ Xl)
{
    const int r = blockIdx.x, t = threadIdx.x;
    float4 v = ((const float4*)x)[r * 256 + t];
    uint32_t h0, l0, h1, l1;
    split2h(v.x, v.y, h0, l0);
    split2h(v.z, v.w, h1, l1);
    Xh[(size_t)r * 512 + 2 * t]     = h0;  Xl[(size_t)r * 512 + 2 * t]     = l0;
    Xh[(size_t)r * 512 + 2 * t + 1] = h1;  Xl[(size_t)r * 512 + 2 * t + 1] = l1;
}

// fused wq/wk/wv: single fp16, [h][sec*64+n][kpair], row stride 512 u32
__global__ void __launch_bounds__(256) conv_wqkv_kernel(const float* __restrict__ wq,
                                                        const float* __restrict__ wk,
                                                        const float* __restrict__ wv,
                                                        uint32_t* __restrict__ dst)
{
    __shared__ float sw[64][65];
    const int k0 = blockIdx.x * 64;
    const int z  = blockIdx.z;
    const int sec = z >> 4, h = z & 15;
    const int t  = threadIdx.x;
    const float* s = (sec == 0 ? wq : sec == 1 ? wk : wv) + (size_t)h * DM * DK;

    #pragma unroll
    for (int i = 0; i < 16; i++) {
        int idx = i * 256 + t;
        int row = idx >> 6, col = idx & 63;
        sw[row][col] = s[(size_t)(k0 + row) * DK + col];
    }
    __syncthreads();
    #pragma unroll
    for (int i = 0; i < 8; i++) {
        int idx = i * 256 + t;
        int n = idx >> 5, kp = idx & 31;
        size_t o = (size_t)h * (192 * 512) + (size_t)(sec * 64 + n) * 512 + k0 / 2 + kp;
        dst[o] = pack2h(sw[2 * kp][n], sw[2 * kp + 1][n]);
    }
}

__global__ void __launch_bounds__(256) conv_wo_kernel(const float* __restrict__ src,
                                                      uint32_t* __restrict__ dst)
{
    __shared__ float sw[64][65];
    const int k0 = blockIdx.x * 64;
    const int n0 = blockIdx.y * 64;
    const int t  = threadIdx.x;

    #pragma unroll
    for (int i = 0; i < 16; i++) {
        int idx = i * 256 + t;
        int row = idx >> 6, col = idx & 63;
        sw[row][col] = src[(size_t)(k0 + row) * DM + n0 + col];
    }
    __syncthreads();
    #pragma unroll
    for (int i = 0; i < 8; i++) {
        int idx = i * 256 + t;
        int n = idx >> 5, kp = idx & 31;
        size_t o = (size_t)(n0 + n) * 512 + k0 / 2 + kp;
        dst[o] = pack2h(sw[2 * kp][n], sw[2 * kp + 1][n]);
    }
}

// ---------------------------------------------------------------------------
// GEMM tile machinery: 128 rows x 64 cols, k-chunk 32, 2-stage cp.async.
// fp16: A split (Ah + optional Al), B single. LDSM loads; B-frag reused
// across both terms (single ldsm per n-block).
// Stage = Ah(2560) + Al(2560) + B(1280) = 6400 u32; 2 stages = 51200 B.
// ---------------------------------------------------------------------------
#define G_STAGE_U32 6400
#define G_SMEM (2 * G_STAGE_U32 * 4)

__device__ __forceinline__ void gemm_stage_load(uint32_t* st,
                                                const uint32_t* Ahg, const uint32_t* Alg,
                                                const uint32_t* Bg,
                                                int kc16, int tid, bool two_term)
{
    #pragma unroll
    for (int i = 0; i < 2; i++) {
        int idx = tid + i * 256;               // 0..511
        int row = idx >> 2, sg = (idx & 3) * 4;
        CPA16(st + row * 20 + sg, Ahg + (size_t)row * 512 + kc16 + sg);
        if (two_term)
            CPA16(st + 2560 + row * 20 + sg, Alg + (size_t)row * 512 + kc16 + sg);
    }
    {
        int row = tid >> 2, sg = (tid & 3) * 4;  // rows 0..63
        CPA16(st + 5120 + row * 20 + sg, Bg + (size_t)row * 512 + kc16 + sg);
    }
}

__device__ __forceinline__ void gemm_core(uint32_t* sm, float (*acc)[4],
                                          const uint32_t* Ahg, const uint32_t* Alg,
                                          const uint32_t* Bg,
                                          int tid, int aoff, int boff, bool two_term)
{
    gemm_stage_load(sm, Ahg, Alg, Bg, 0, tid, two_term);
    CP_COMMIT();

    for (int c = 0; c < 32; c++) {
        if (c < 31) {
            gemm_stage_load(sm + ((c + 1) & 1) * G_STAGE_U32,
                            Ahg, Alg, Bg, (c + 1) * 16, tid, two_term);
            CP_COMMIT();
            CP_WAIT(1);
        } else {
            CP_WAIT(0);
        }
        __syncthreads();

        const uint32_t* p  = sm + (c & 1) * G_STAGE_U32;
        const uint32_t* Ah = p;
        const uint32_t* Al = p + 2560;
        const uint32_t* Bs = p + 5120;

        #pragma unroll
        for (int ks = 0; ks < 2; ks++) {
            uint32_t ah[4], al[4];
            ldsm_x4(ah, Ah + aoff + ks * 8);
            if (two_term) ldsm_x4(al, Al + aoff + ks * 8);
            #pragma unroll
            for (int nbp = 0; nbp < 4; nbp++) {
                uint32_t b[4];
                ldsm_x4(b, Bs + boff + nbp * 320 + ks * 8);
                mma_f16(acc[2 * nbp],     ah, b);
                mma_f16(acc[2 * nbp + 1], ah, b + 2);
                if (two_term) {
                    mma_f16(acc[2 * nbp],     al, b);
                    mma_f16(acc[2 * nbp + 1], al, b + 2);
                }
            }
        }
        __syncthreads();
    }
}

// ---------------------------------------------------------------------------
// QKV GEMM: CTA = (row-tile, head, section). section: 0=Q, 1=K, 2=V.
// Q/K use 2-term (feeds softmax); V single-term (rounded to fp16 anyway).
// ---------------------------------------------------------------------------
__global__ void __launch_bounds__(256, 3) qkv_kernel(const uint32_t* __restrict__ Xh,
                                                     const uint32_t* __restrict__ Xl,
                                                     const uint32_t* __restrict__ W,
                                                     const float* __restrict__ qb,
                                                     const float* __restrict__ kb,
                                                     const float* __restrict__ vb,
                                                     uint32_t* __restrict__ oQh,
                                                     uint32_t* __restrict__ oQl,
                                                     uint32_t* __restrict__ oKh,
                                                     uint32_t* __restrict__ oVt)
{
    extern __shared__ uint32_t sm[];
    const int m0  = blockIdx.x * 128;
    const int h   = blockIdx.y;
    const int sec = blockIdx.z;
    const int tid = threadIdx.x;
    const int wid = tid >> 5, lane = tid & 31, g = lane >> 2, t = lane & 3;
    const int lrow = lane & 7;
    const int aoff = (wid * 16 + lrow + ((lane >> 3) & 1) * 8) * 20 + (lane >> 4) * 4;
    const int boff = (lrow + ((lane >> 4) & 1) * 8) * 20 + ((lane >> 3) & 1) * 4;

    float acc[8][4] = {};
    const bool two_term = (sec != 2);

    gemm_core(sm, acc,
              Xh + (size_t)m0 * 512, Xl + (size_t)m0 * 512,
              W + ((size_t)h * 192 + sec * 64) * 512,
              tid, aoff, boff, two_term);

    const int r = wid * 16 + g;
    const int grow = m0 + r;

    if (sec == 0) {
        // Q: split fp16, pre-scaled 0.125
        #pragma unroll
        for (int nb = 0; nb < 8; nb++) {
            int col = nb * 8 + 2 * t;
            float b0 = qb[h * DK + col], b1 = qb[h * DK + col + 1];
            uint32_t h0, l0, h1, l1;
            split2h((acc[nb][0] + b0) * 0.125f, (acc[nb][1] + b1) * 0.125f, h0, l0);
            split2h((acc[nb][2] + b0) * 0.125f, (acc[nb][3] + b1) * 0.125f, h1, l1);
            size_t base = ((size_t)h * NN + grow) * QKS + nb * 4 + t;
            oQh[base] = h0;            oQl[base] = l0;
            oQh[base + 8 * QKS] = h1;  oQl[base + 8 * QKS] = l1;
        }
    } else if (sec == 1) {
        // K: single fp16
        #pragma unroll
        for (int nb = 0; nb < 8; nb++) {
            int col = nb * 8 + 2 * t;
            float b0 = kb[h * DK + col], b1 = kb[h * DK + col + 1];
            size_t base = ((size_t)h * NN + grow) * QKS + nb * 4 + t;
            oKh[base]           = pack2h(acc[nb][0] + b0, acc[nb][1] + b1);
            oKh[base + 8 * QKS] = pack2h(acc[nb][2] + b0, acc[nb][3] + b1);
        }
    } else {
        // V: fp16 transpose via smem ([64 dk][132 fp16] = stride 66 u32)
        uint16_t* Vs16 = (uint16_t*)sm;
        #pragma unroll
        for (int nb = 0; nb < 8; nb++) {
            int col = nb * 8 + 2 * t;
            float b0 = vb[h * DK + col], b1 = vb[h * DK + col + 1];
            Vs16[(col)     * 132 + r]     = f16bits(acc[nb][0] + b0);
            Vs16[(col + 1) * 132 + r]     = f16bits(acc[nb][1] + b1);
            Vs16[(col)     * 132 + r + 8] = f16bits(acc[nb][2] + b0);
            Vs16[(col + 1) * 132 + r + 8] = f16bits(acc[nb][3] + b1);
        }
        __syncthreads();
        #pragma unroll
        for (int i = 0; i < 16; i++) {
            int idx = tid + i * 256;
            int dk = idx >> 6, cc = idx & 63;
            oVt[((size_t)h * DK + dk) * (NN / 2) + m0 / 2 + cc] = sm[dk * 66 + cc];
        }
    }
}

// ---------------------------------------------------------------------------
// Out projection + bias + residual: CTA = (row-tile, 64-col tile).
// A = split concat (Ch+Cl), B = Wo single fp16.
// ---------------------------------------------------------------------------
__global__ void __launch_bounds__(256, 3) outproj_kernel(const uint32_t* __restrict__ Ahg,
                                                         const uint32_t* __restrict__ Alg,
                                                         const uint32_t* __restrict__ Bg,
                                                         const float* __restrict__ x,
                                                         const float* __restrict__ ob,
                                                         float* __restrict__ out)
{
    extern __shared__ uint32_t sm[];
    const int m0 = blockIdx.x * 128;
    const int c0 = blockIdx.y * 64;
    const int tid = threadIdx.x;
    const int wid = tid >> 5, lane = tid & 31, g = lane >> 2, t = lane & 3;
    const int lrow = lane & 7;
    const int aoff = (wid * 16 + lrow + ((lane >> 3) & 1) * 8) * 20 + (lane >> 4) * 4;
    const int boff = (lrow + ((lane >> 4) & 1) * 8) * 20 + ((lane >> 3) & 1) * 4;

    float acc[8][4] = {};

    gemm_core(sm, acc,
              Ahg + (size_t)m0 * 512, Alg + (size_t)m0 * 512,
              Bg + (size_t)c0 * 512,
              tid, aoff, boff, true);

    const int r0 = m0 + wid * 16 + g;
    #pragma unroll
    for (int nb = 0; nb < 8; nb++) {
        int col = c0 + nb * 8 + 2 * t;
        float b0 = ob[col], b1 = ob[col + 1];
        const float* xr0 = &x[(size_t)r0 * DM + col];
        const float* xr1 = &x[(size_t)(r0 + 8) * DM + col];
        float2 v0 = make_float2(acc[nb][0] + b0 + xr0[0], acc[nb][1] + b1 + xr0[1]);
        float2 v1 = make_float2(acc[nb][2] + b0 + xr1[0], acc[nb][3] + b1 + xr1[1]);
        *(float2*)&out[(size_t)r0 * DM + col]       = v0;
        *(float2*)&out[(size_t)(r0 + 8) * DM + col] = v1;
    }
}

// ---------------------------------------------------------------------------
// Flash attention: fp16 QK (2-term, Q split / K single, B-frag reused) + fp16 PV.
// buf = Kh[64][36] + Vt[64][36] = 4608 u32 per stage.
// ---------------------------------------------------------------------------
#define ATTN_BUF_U32 (2 * 64 * 36)
#define ATTN_SMEM_BYTES (2 * ATTN_BUF_U32 * 4)

__device__ __forceinline__ void attn_stage(uint32_t* dst, const uint32_t* Kh,
                                           const uint32_t* Vt,
                                           int h, int t0, int tid)
{
    const uint32_t* sKh = Kh + ((size_t)h * NN + t0) * QKS;
    const uint32_t* sVt = Vt + (size_t)h * DK * (NN / 2) + t0 / 2;
    for (int idx = tid; idx < 1088; idx += 256) {
        if (idx < 576) {
            CPA16(dst + idx * 4, sKh + idx * 4);
        } else {
            int j = idx - 576;
            int dk = j >> 3, c = (j & 7) * 4;
            CPA16(dst + 2304 + dk * 36 + c, sVt + (size_t)dk * (NN / 2) + c);
        }
    }
}

__global__ void __launch_bounds__(256, 2) attn_kernel(const uint32_t* __restrict__ Qh,
                                                      const uint32_t* __restrict__ Ql,
                                                      const uint32_t* __restrict__ Kh,
                                                      const uint32_t* __restrict__ Vt,
                                                      uint32_t* __restrict__ Ch,
                                                      uint32_t* __restrict__ Cl)
{
    extern __shared__ uint32_t sm[];
    const int h  = blockIdx.y;
    const int q0 = blockIdx.x * 128;
    const int tid = threadIdx.x;
    const int wid = tid >> 5, lane = tid & 31, g = lane >> 2, t = lane & 3;
    const int lrow = lane & 7;
    const int boff = (lrow + ((lane >> 4) & 1) * 8) * 36 + ((lane >> 3) & 1) * 4;

    attn_stage(sm, Kh, Vt, h, 0, tid);
    CP_COMMIT();

    uint32_t ah[4][4], al[4][4];
    {
        const uint32_t* qh = Qh + ((size_t)h * NN + q0 + wid * 16 + g) * QKS;
        const uint32_t* ql = Ql + ((size_t)h * NN + q0 + wid * 16 + g) * QKS;
        #pragma unroll
        for (int ks = 0; ks < 4; ks++) {
            ah[ks][0] = qh[ks * 8 + t];       ah[ks][1] = qh[8 * QKS + ks * 8 + t];
            ah[ks][2] = qh[ks * 8 + t + 4];   ah[ks][3] = qh[8 * QKS + ks * 8 + t + 4];
            al[ks][0] = ql[ks * 8 + t];       al[ks][1] = ql[8 * QKS + ks * 8 + t];
            al[ks][2] = ql[ks * 8 + t + 4];   al[ks][3] = ql[8 * QKS + ks * 8 + t + 4];
        }
    }

    float o[8][4] = {};
    float m0 = -1e30f, m1 = -1e30f, l0 = 0.f, l1 = 0.f;

    for (int tt = 0; tt < NN / 64; tt++) {
        uint32_t* buf = sm + (tt & 1) * ATTN_BUF_U32;
        if (tt + 1 < NN / 64) {
            attn_stage(sm + ((tt + 1) & 1) * ATTN_BUF_U32, Kh, Vt, h, (tt + 1) * 64, tid);
            CP_COMMIT();
            CP_WAIT(1);
        } else {
            CP_WAIT(0);
        }
        __syncthreads();

        const uint32_t* kh = buf;
        const uint32_t* vs = buf + 2304;

        float s[8][4] = {};
        #pragma unroll
        for (int ks = 0; ks < 4; ks++) {
            #pragma unroll
            for (int nbp = 0; nbp < 4; nbp++) {
                uint32_t b[4];
                ldsm_x4(b, kh + boff + nbp * 576 + ks * 8);
                mma_f16(s[2 * nbp],     ah[ks], b);
                mma_f16(s[2 * nbp + 1], ah[ks], b + 2);
                mma_f16(s[2 * nbp],     al[ks], b);
                mma_f16(s[2 * nbp + 1], al[ks], b + 2);
            }
        }

        float mx0 = -1e30f, mx1 = -1e30f;
        #pragma unroll
        for (int nb = 0; nb < 8; nb++) {
            mx0 = fmaxf(mx0, fmaxf(s[nb][0], s[nb][1]));
            mx1 = fmaxf(mx1, fmaxf(s[nb][2], s[nb][3]));
        }
        mx0 = fmaxf(mx0, __shfl_xor_sync(0xffffffffu, mx0, 1));
        mx0 = fmaxf(mx0, __shfl_xor_sync(0xffffffffu, mx0, 2));
        mx1 = fmaxf(mx1, __shfl_xor_sync(0xffffffffu, mx1, 1));
        mx1 = fmaxf(mx1, __shfl_xor_sync(0xffffffffu, mx1, 2));

        float nm0 = fmaxf(m0, mx0), nm1 = fmaxf(m1, mx1);
        float sc0 = __expf(m0 - nm0), sc1 = __expf(m1 - nm1);
        float sum0 = 0.f, sum1 = 0.f;
        #pragma unroll
        for (int nb = 0; nb < 8; nb++) {
            s[nb][0] = __expf(s[nb][0] - nm0);
            s[nb][1] = __expf(s[nb][1] - nm0);
            s[nb][2] = __expf(s[nb][2] - nm1);
            s[nb][3] = __expf(s[nb][3] - nm1);
            sum0 += s[nb][0] + s[nb][1];
            sum1 += s[nb][2] + s[nb][3];
        }
        sum0 += __shfl_xor_sync(0xffffffffu, sum0, 1);
        sum0 += __shfl_xor_sync(0xffffffffu, sum0, 2);
        sum1 += __shfl_xor_sync(0xffffffffu, sum1, 1);
        sum1 += __shfl_xor_sync(0xffffffffu, sum1, 2);
        l0 = l0 * sc0 + sum0;  m0 = nm0;
        l1 = l1 * sc1 + sum1;  m1 = nm1;
        #pragma unroll
        for (int nb = 0; nb < 8; nb++) {
            o[nb][0] *= sc0; o[nb][1] *= sc0;
            o[nb][2] *= sc1; o[nb][3] *= sc1;
        }

        // O += P V (fp16)
        #pragma unroll
        for (int kp = 0; kp < 4; kp++) {
            uint32_t ap[4];
            ap[0] = pack2h(s[2 * kp][0],     s[2 * kp][1]);
            ap[1] = pack2h(s[2 * kp][2],     s[2 * kp][3]);
            ap[2] = pack2h(s[2 * kp + 1][0], s[2 * kp + 1][1]);
            ap[3] = pack2h(s[2 * kp + 1][2], s[2 * kp + 1][3]);
            #pragma unroll
            for (int nbp = 0; nbp < 4; nbp++) {
                uint32_t b[4];
                ldsm_x4(b, vs + boff + nbp * 576 + kp * 8);
                mma_f16(o[2 * nbp],     ap, b);
                mma_f16(o[2 * nbp + 1], ap, b + 2);
            }
        }
        __syncthreads();
    }

    // epilogue: write concat as split fp16 pairs
    const float inv0 = 1.0f / l0, inv1 = 1.0f / l1;
    const int r0 = q0 + wid * 16 + g;
    #pragma unroll
    for (int nb = 0; nb < 8; nb++) {
        int cpi = h * 32 + nb * 4 + t;
        uint32_t h0, lo0, h1, lo1;
        split2h(o[nb][0] * inv0, o[nb][1] * inv0, h0, lo0);
        split2h(o[nb][2] * inv1, o[nb][3] * inv1, h1, lo1);
        Ch[(size_t)r0 * 512 + cpi]       = h0;  Cl[(size_t)r0 * 512 + cpi]       = lo0;
        Ch[(size_t)(r0 + 8) * 512 + cpi] = h1;  Cl[(size_t)(r0 + 8) * 512 + cpi] = lo1;
    }
}

// ---------------------------------------------------------------------------
// LayerNorm, one block per row
// ---------------------------------------------------------------------------
__global__ void __launch_bounds__(256) ln_kernel(const float* __restrict__ pre,
                                                 const float* __restrict__ alpha,
                                                 const float* __restrict__ beta,
                                                 float* __restrict__ out)
{
    const int row = blockIdx.x;
    const int tid = threadIdx.x;
    const float4 v = ((const float4*)(pre + (size_t)row * DM))[tid];

    float sum = v.x + v.y + v.z + v.w;
    float sq  = v.x * v.x + v.y * v.y + v.z * v.z + v.w * v.w;

    #pragma unroll
    for (int d = 16; d >= 1; d >>= 1) {
        sum += __shfl_xor_sync(0xffffffffu, sum, d);
        sq  += __shfl_xor_sync(0xffffffffu, sq,  d);
    }

    __shared__ float ssum[8], ssq[8];
    __shared__ float s_mu, s_rstd;
    int warp = tid >> 5, lane = tid & 31;
    if (lane == 0) { ssum[warp] = sum; ssq[warp] = sq; }
    __syncthreads();
    if (tid == 0) {
        float ts = 0.f, tq = 0.f;
        #pragma unroll
        for (int i = 0; i < 8; i++) { ts += ssum[i]; tq += ssq[i]; }
        float mu  = ts * (1.0f / DM);
        float var = tq * (1.0f / DM) - mu * mu;
        s_mu = mu;
        s_rstd = rsqrtf(var + LN_EPS);
    }
    __syncthreads();

    const float mu = s_mu, rstd = s_rstd;
    const float4 a4 = ((const float4*)alpha)[tid];
    const float4 b4 = ((const float4*)beta)[tid];
    float4 r;
    r.x = a4.x * (v.x - mu) * rstd + b4.x;
    r.y = a4.y * (v.y - mu) * rstd + b4.y;
    r.z = a4.z * (v.z - mu) * rstd + b4.z;
    r.w = a4.w * (v.w - mu) * rstd + b4.w;
    ((float4*)(out + (size_t)row * DM))[tid] = r;
}

// ---------------------------------------------------------------------------
extern "C" void kernel_launch(void* const* d_in, const int* in_sizes, int n_in,
                              void* d_out, int out_size)
{
    const float* x     = (const float*)d_in[0];
    const float* wq    = (const float*)d_in[1];
    const float* qb    = (const float*)d_in[2];
    const float* wk    = (const float*)d_in[3];
    const float* kb    = (const float*)d_in[4];
    const float* wv    = (const float*)d_in[5];
    const float* vb    = (const float*)d_in[6];
    const float* wo    = (const float*)d_in[7];
    const float* ob    = (const float*)d_in[8];
    const float* alpha = (const float*)d_in[9];
    const float* beta  = (const float*)d_in[10];
    float* out = (float*)d_out;

    uint32_t *Xh, *Xl, *Wq, *Wo;
    uint32_t *Qh, *Ql, *Kh, *Vt, *Ch, *Cl;
    float *pre;
    cudaGetSymbolAddress((void**)&Xh,  g_Xh);
    cudaGetSymbolAddress((void**)&Xl,  g_Xl);
    cudaGetSymbolAddress((void**)&Wq,  g_Wq);
    cudaGetSymbolAddress((void**)&Wo,  g_Wo);
    cudaGetSymbolAddress((void**)&Qh,  g_Qh);
    cudaGetSymbolAddress((void**)&Ql,  g_Ql);
    cudaGetSymbolAddress((void**)&Kh,  g_Kh);
    cudaGetSymbolAddress((void**)&Vt,  g_Vt);
    cudaGetSymbolAddress((void**)&Ch,  g_Ch);
    cudaGetSymbolAddress((void**)&Cl,  g_Cl);
    cudaGetSymbolAddress((void**)&pre, g_pre);

    cudaFuncSetAttribute(qkv_kernel,
                         cudaFuncAttributeMaxDynamicSharedMemorySize, G_SMEM);
    cudaFuncSetAttribute(outproj_kernel,
                         cudaFuncAttributeMaxDynamicSharedMemorySize, G_SMEM);
    cudaFuncSetAttribute(attn_kernel,
                         cudaFuncAttributeMaxDynamicSharedMemorySize, ATTN_SMEM_BYTES);

    // conversions
    conv_x_kernel<<<NN, 256>>>(x, Xh, Xl);
    conv_wqkv_kernel<<<dim3(16, 1, 48), 256>>>(wq, wk, wv, Wq);
    conv_wo_kernel<<<dim3(16, 16, 1), 256>>>(wo, Wo);

    qkv_kernel<<<dim3(NN / 128, NH, 3), 256, G_SMEM>>>(Xh, Xl, Wq,
                                                       qb, kb, vb,
                                                       Qh, Ql, Kh, Vt);

    attn_kernel<<<dim3(NN / 128, NH), 256, ATTN_SMEM_BYTES>>>(Qh, Ql, Kh, Vt, Ch, Cl);

    outproj_kernel<<<dim3(NN / 128, DM / 64), 256, G_SMEM>>>(Ch, Cl, Wo,
                                                             x, ob, pre);

    ln_kernel<<<NN, 256>>>(pre, alpha, beta, out);
}

// round 12
// speedup vs baseline: 2.2194x; 1.0726x over previous
#include <cuda_runtime.h>
#include <cuda_fp16.h>
#include <cstdint>

#define NN 2048
#define DM 1024
#define NH 16
#define DK 64
#define LN_EPS 1e-5f
#define QKS 36   // u32 row stride for packed Q/K (32 pairs + 4 pad)

// Scratch (device globals) — fp16 pair arrays (u32 = f16x2)
__device__ uint32_t g_Xh[(size_t)NN * 512];
__device__ uint32_t g_Xl[(size_t)NN * 512];
__device__ uint32_t g_Wq[(size_t)NH * 192 * 512];     // single fp16
__device__ uint32_t g_Wo[(size_t)DM * 512];           // single fp16
__device__ uint32_t g_Qh[(size_t)NH * NN * QKS];
__device__ uint32_t g_Ql[(size_t)NH * NN * QKS];
__device__ uint32_t g_Kh[(size_t)NH * NN * QKS];      // single fp16
__device__ uint32_t g_Vt[(size_t)NH * DK * (NN / 2)]; // fp16 [h][dk][keypair]
__device__ uint32_t g_Ch[(size_t)NN * 512];           // concat, single fp16
__device__ float    g_pre[(size_t)NN * DM];

// ---------------------------------------------------------------------------
// helpers
// ---------------------------------------------------------------------------
__device__ __forceinline__ uint32_t pack2h(float e0, float e1) {  // f16x2: e0 low
    uint32_t r;
    asm("cvt.rn.f16x2.f32 %0, %1, %2;" : "=r"(r) : "f"(e1), "f"(e0));
    return r;
}
__device__ __forceinline__ uint16_t f16bits(float v) {
    uint16_t u;
    asm("cvt.rn.f16.f32 %0, %1;" : "=h"(u) : "f"(v));
    return u;
}
// split pair (x0,x1) into hi-f16x2 + lo-f16x2 residual
__device__ __forceinline__ void split2h(float x0, float x1, uint32_t& hi, uint32_t& lo) {
    __half2 h = __floats2half2_rn(x0, x1);
    float2 hf = __half22float2(h);
    __half2 l = __floats2half2_rn(x0 - hf.x, x1 - hf.y);
    hi = *(uint32_t*)&h;
    lo = *(uint32_t*)&l;
}
__device__ __forceinline__ void mma_f16(float* c, const uint32_t* a, const uint32_t* b) {
    asm("mma.sync.aligned.m16n8k16.row.col.f32.f16.f16.f32 "
        "{%0,%1,%2,%3}, {%4,%5,%6,%7}, {%8,%9}, {%0,%1,%2,%3};\n"
        : "+f"(c[0]), "+f"(c[1]), "+f"(c[2]), "+f"(c[3])
        : "r"(a[0]), "r"(a[1]), "r"(a[2]), "r"(a[3]), "r"(b[0]), "r"(b[1]));
}
__device__ __forceinline__ void ldsm_x4(uint32_t* r, const uint32_t* p) {
    uint32_t addr = (uint32_t)__cvta_generic_to_shared(p);
    asm volatile("ldmatrix.sync.aligned.m8n8.x4.shared.b16 {%0,%1,%2,%3}, [%4];"
        : "=r"(r[0]), "=r"(r[1]), "=r"(r[2]), "=r"(r[3]) : "r"(addr));
}
#define CPA16(sptr, gptr) do {                                                 \
    uint32_t _s = (uint32_t)__cvta_generic_to_shared(sptr);                    \
    asm volatile("cp.async.cg.shared.global [%0], [%1], 16;" :: "r"(_s), "l"(gptr)); \
} while (0)
#define CP_COMMIT() asm volatile("cp.async.commit_group;")
#define CP_WAIT(n)  asm volatile("cp.async.wait_group %0;" :: "n"(n))

// ---------------------------------------------------------------------------
// conversion kernels
// ---------------------------------------------------------------------------
__global__ void __launch_bounds__(256) conv_x_kernel(const float* __restrict__ x,
                                                     uint32_t* __restrict__ Xh,
                                                     uint32_t* __restrict__ Xl)
{
    const int r = blockIdx.x, t = threadIdx.x;
    float4 v = ((const float4*)x)[r * 256 + t];
    uint32_t h0, l0, h1, l1;
    split2h(v.x, v.y, h0, l0);
    split2h(v.z, v.w, h1, l1);
    Xh[(size_t)r * 512 + 2 * t]     = h0;  Xl[(size_t)r * 512 + 2 * t]     = l0;
    Xh[(size_t)r * 512 + 2 * t + 1] = h1;  Xl[(size_t)r * 512 + 2 * t + 1] = l1;
}

// fused wq/wk/wv: single fp16, [h][sec*64+n][kpair], row stride 512 u32
__global__ void __launch_bounds__(256) conv_wqkv_kernel(const float* __restrict__ wq,
                                                        const float* __restrict__ wk,
                                                        const float* __restrict__ wv,
                                                        uint32_t* __restrict__ dst)
{
    __shared__ float sw[64][65];
    const int k0 = blockIdx.x * 64;
    const int z  = blockIdx.z;
    const int sec = z >> 4, h = z & 15;
    const int t  = threadIdx.x;
    const float* s = (sec == 0 ? wq : sec == 1 ? wk : wv) + (size_t)h * DM * DK;

    #pragma unroll
    for (int i = 0; i < 16; i++) {
        int idx = i * 256 + t;
        int row = idx >> 6, col = idx & 63;
        sw[row][col] = s[(size_t)(k0 + row) * DK + col];
    }
    __syncthreads();
    #pragma unroll
    for (int i = 0; i < 8; i++) {
        int idx = i * 256 + t;
        int n = idx >> 5, kp = idx & 31;
        size_t o = (size_t)h * (192 * 512) + (size_t)(sec * 64 + n) * 512 + k0 / 2 + kp;
        dst[o] = pack2h(sw[2 * kp][n], sw[2 * kp + 1][n]);
    }
}

__global__ void __launch_bounds__(256) conv_wo_kernel(const float* __restrict__ src,
                                                      uint32_t* __restrict__ dst)
{
    __shared__ float sw[64][65];
    const int k0 = blockIdx.x * 64;
    const int n0 = blockIdx.y * 64;
    const int t  = threadIdx.x;

    #pragma unroll
    for (int i = 0; i < 16; i++) {
        int idx = i * 256 + t;
        int row = idx >> 6, col = idx & 63;
        sw[row][col] = src[(size_t)(k0 + row) * DM + n0 + col];
    }
    __syncthreads();
    #pragma unroll
    for (int i = 0; i < 8; i++) {
        int idx = i * 256 + t;
        int n = idx >> 5, kp = idx & 31;
        size_t o = (size_t)(n0 + n) * 512 + k0 / 2 + kp;
        dst[o] = pack2h(sw[2 * kp][n], sw[2 * kp + 1][n]);
    }
}

// ---------------------------------------------------------------------------
// GEMM tile machinery: 128 rows x 64 cols, k-chunk 32, 2-stage cp.async.
// fp16: A split (Ah + optional Al), B single. LDSM loads; B-frag reused
// across terms. Stage = Ah(2560) + Al(2560) + B(1280) = 6400 u32.
// ---------------------------------------------------------------------------
#define G_STAGE_U32 6400
#define G_SMEM (2 * G_STAGE_U32 * 4)

__device__ __forceinline__ void gemm_stage_load(uint32_t* st,
                                                const uint32_t* Ahg, const uint32_t* Alg,
                                                const uint32_t* Bg,
                                                int kc16, int tid, bool two_term)
{
    #pragma unroll
    for (int i = 0; i < 2; i++) {
        int idx = tid + i * 256;               // 0..511
        int row = idx >> 2, sg = (idx & 3) * 4;
        CPA16(st + row * 20 + sg, Ahg + (size_t)row * 512 + kc16 + sg);
        if (two_term)
            CPA16(st + 2560 + row * 20 + sg, Alg + (size_t)row * 512 + kc16 + sg);
    }
    {
        int row = tid >> 2, sg = (tid & 3) * 4;  // rows 0..63
        CPA16(st + 5120 + row * 20 + sg, Bg + (size_t)row * 512 + kc16 + sg);
    }
}

__device__ __forceinline__ void gemm_core(uint32_t* sm, float (*acc)[4],
                                          const uint32_t* Ahg, const uint32_t* Alg,
                                          const uint32_t* Bg,
                                          int tid, int aoff, int boff, bool two_term)
{
    gemm_stage_load(sm, Ahg, Alg, Bg, 0, tid, two_term);
    CP_COMMIT();

    for (int c = 0; c < 32; c++) {
        if (c < 31) {
            gemm_stage_load(sm + ((c + 1) & 1) * G_STAGE_U32,
                            Ahg, Alg, Bg, (c + 1) * 16, tid, two_term);
            CP_COMMIT();
            CP_WAIT(1);
        } else {
            CP_WAIT(0);
        }
        __syncthreads();

        const uint32_t* p  = sm + (c & 1) * G_STAGE_U32;
        const uint32_t* Ah = p;
        const uint32_t* Al = p + 2560;
        const uint32_t* Bs = p + 5120;

        #pragma unroll
        for (int ks = 0; ks < 2; ks++) {
            uint32_t ah[4], al[4];
            ldsm_x4(ah, Ah + aoff + ks * 8);
            if (two_term) ldsm_x4(al, Al + aoff + ks * 8);
            #pragma unroll
            for (int nbp = 0; nbp < 4; nbp++) {
                uint32_t b[4];
                ldsm_x4(b, Bs + boff + nbp * 320 + ks * 8);
                mma_f16(acc[2 * nbp],     ah, b);
                mma_f16(acc[2 * nbp + 1], ah, b + 2);
                if (two_term) {
                    mma_f16(acc[2 * nbp],     al, b);
                    mma_f16(acc[2 * nbp + 1], al, b + 2);
                }
            }
        }
        __syncthreads();
    }
}

// ---------------------------------------------------------------------------
// QKV GEMM: CTA = (row-tile, head, section). section: 0=Q, 1=K, 2=V.
// Q/K use 2-term (feeds softmax); V single-term (rounded to fp16 anyway).
// ---------------------------------------------------------------------------
__global__ void __launch_bounds__(256, 3) qkv_kernel(const uint32_t* __restrict__ Xh,
                                                     const uint32_t* __restrict__ Xl,
                                                     const uint32_t* __restrict__ W,
                                                     const float* __restrict__ qb,
                                                     const float* __restrict__ kb,
                                                     const float* __restrict__ vb,
                                                     uint32_t* __restrict__ oQh,
                                                     uint32_t* __restrict__ oQl,
                                                     uint32_t* __restrict__ oKh,
                                                     uint32_t* __restrict__ oVt)
{
    extern __shared__ uint32_t sm[];
    const int m0  = blockIdx.x * 128;
    const int h   = blockIdx.y;
    const int sec = blockIdx.z;
    const int tid = threadIdx.x;
    const int wid = tid >> 5, lane = tid & 31, g = lane >> 2, t = lane & 3;
    const int lrow = lane & 7;
    const int aoff = (wid * 16 + lrow + ((lane >> 3) & 1) * 8) * 20 + (lane >> 4) * 4;
    const int boff = (lrow + ((lane >> 4) & 1) * 8) * 20 + ((lane >> 3) & 1) * 4;

    float acc[8][4] = {};
    const bool two_term = (sec != 2);

    gemm_core(sm, acc,
              Xh + (size_t)m0 * 512, Xl + (size_t)m0 * 512,
              W + ((size_t)h * 192 + sec * 64) * 512,
              tid, aoff, boff, two_term);

    const int r = wid * 16 + g;
    const int grow = m0 + r;

    if (sec == 0) {
        // Q: split fp16, pre-scaled 0.125
        #pragma unroll
        for (int nb = 0; nb < 8; nb++) {
            int col = nb * 8 + 2 * t;
            float b0 = qb[h * DK + col], b1 = qb[h * DK + col + 1];
            uint32_t h0, l0, h1, l1;
            split2h((acc[nb][0] + b0) * 0.125f, (acc[nb][1] + b1) * 0.125f, h0, l0);
            split2h((acc[nb][2] + b0) * 0.125f, (acc[nb][3] + b1) * 0.125f, h1, l1);
            size_t base = ((size_t)h * NN + grow) * QKS + nb * 4 + t;
            oQh[base] = h0;            oQl[base] = l0;
            oQh[base + 8 * QKS] = h1;  oQl[base + 8 * QKS] = l1;
        }
    } else if (sec == 1) {
        // K: single fp16
        #pragma unroll
        for (int nb = 0; nb < 8; nb++) {
            int col = nb * 8 + 2 * t;
            float b0 = kb[h * DK + col], b1 = kb[h * DK + col + 1];
            size_t base = ((size_t)h * NN + grow) * QKS + nb * 4 + t;
            oKh[base]           = pack2h(acc[nb][0] + b0, acc[nb][1] + b1);
            oKh[base + 8 * QKS] = pack2h(acc[nb][2] + b0, acc[nb][3] + b1);
        }
    } else {
        // V: fp16 transpose via smem ([64 dk][132 fp16] = stride 66 u32)
        uint16_t* Vs16 = (uint16_t*)sm;
        #pragma unroll
        for (int nb = 0; nb < 8; nb++) {
            int col = nb * 8 + 2 * t;
            float b0 = vb[h * DK + col], b1 = vb[h * DK + col + 1];
            Vs16[(col)     * 132 + r]     = f16bits(acc[nb][0] + b0);
            Vs16[(col + 1) * 132 + r]     = f16bits(acc[nb][1] + b1);
            Vs16[(col)     * 132 + r + 8] = f16bits(acc[nb][2] + b0);
            Vs16[(col + 1) * 132 + r + 8] = f16bits(acc[nb][3] + b1);
        }
        __syncthreads();
        #pragma unroll
        for (int i = 0; i < 16; i++) {
            int idx = tid + i * 256;
            int dk = idx >> 6, cc = idx & 63;
            oVt[((size_t)h * DK + dk) * (NN / 2) + m0 / 2 + cc] = sm[dk * 66 + cc];
        }
    }
}

// ---------------------------------------------------------------------------
// Out projection + bias + residual: CTA = (row-tile, 64-col tile).
// A = concat single fp16, B = Wo single fp16 (1-term).
// ---------------------------------------------------------------------------
__global__ void __launch_bounds__(256, 3) outproj_kernel(const uint32_t* __restrict__ Ahg,
                                                         const uint32_t* __restrict__ Bg,
                                                         const float* __restrict__ x,
                                                         const float* __restrict__ ob,
                                                         float* __restrict__ out)
{
    extern __shared__ uint32_t sm[];
    const int m0 = blockIdx.x * 128;
    const int c0 = blockIdx.y * 64;
    const int tid = threadIdx.x;
    const int wid = tid >> 5, lane = tid & 31, g = lane >> 2, t = lane & 3;
    const int lrow = lane & 7;
    const int aoff = (wid * 16 + lrow + ((lane >> 3) & 1) * 8) * 20 + (lane >> 4) * 4;
    const int boff = (lrow + ((lane >> 4) & 1) * 8) * 20 + ((lane >> 3) & 1) * 4;

    float acc[8][4] = {};

    gemm_core(sm, acc,
              Ahg + (size_t)m0 * 512, Ahg + (size_t)m0 * 512,
              Bg + (size_t)c0 * 512,
              tid, aoff, boff, false);

    const int r0 = m0 + wid * 16 + g;
    #pragma unroll
    for (int nb = 0; nb < 8; nb++) {
        int col = c0 + nb * 8 + 2 * t;
        float b0 = ob[col], b1 = ob[col + 1];
        const float* xr0 = &x[(size_t)r0 * DM + col];
        const float* xr1 = &x[(size_t)(r0 + 8) * DM + col];
        float2 v0 = make_float2(acc[nb][0] + b0 + xr0[0], acc[nb][1] + b1 + xr0[1]);
        float2 v1 = make_float2(acc[nb][2] + b0 + xr1[0], acc[nb][3] + b1 + xr1[1]);
        *(float2*)&out[(size_t)r0 * DM + col]       = v0;
        *(float2*)&out[(size_t)(r0 + 8) * DM + col] = v1;
    }
}

// ---------------------------------------------------------------------------
// Flash attention: fp16 QK (2-term, Q split / K single, B-frag reused) + fp16 PV.
// buf = Kh[64][36] + Vt[64][36] = 4608 u32 per stage.
// ---------------------------------------------------------------------------
#define ATTN_BUF_U32 (2 * 64 * 36)
#define ATTN_SMEM_BYTES (2 * ATTN_BUF_U32 * 4)

__device__ __forceinline__ void attn_stage(uint32_t* dst, const uint32_t* Kh,
                                           const uint32_t* Vt,
                                           int h, int t0, int tid)
{
    const uint32_t* sKh = Kh + ((size_t)h * NN + t0) * QKS;
    const uint32_t* sVt = Vt + (size_t)h * DK * (NN / 2) + t0 / 2;
    for (int idx = tid; idx < 1088; idx += 256) {
        if (idx < 576) {
            CPA16(dst + idx * 4, sKh + idx * 4);
        } else {
            int j = idx - 576;
            int dk = j >> 3, c = (j & 7) * 4;
            CPA16(dst + 2304 + dk * 36 + c, sVt + (size_t)dk * (NN / 2) + c);
        }
    }
}

__global__ void __launch_bounds__(256, 2) attn_kernel(const uint32_t* __restrict__ Qh,
                                                      const uint32_t* __restrict__ Ql,
                                                      const uint32_t* __restrict__ Kh,
                                                      const uint32_t* __restrict__ Vt,
                                                      uint32_t* __restrict__ Ch)
{
    extern __shared__ uint32_t sm[];
    const int h  = blockIdx.y;
    const int q0 = blockIdx.x * 128;
    const int tid = threadIdx.x;
    const int wid = tid >> 5, lane = tid & 31, g = lane >> 2, t = lane & 3;
    const int lrow = lane & 7;
    const int boff = (lrow + ((lane >> 4) & 1) * 8) * 36 + ((lane >> 3) & 1) * 4;

    attn_stage(sm, Kh, Vt, h, 0, tid);
    CP_COMMIT();

    uint32_t ah[4][4], al[4][4];
    {
        const uint32_t* qh = Qh + ((size_t)h * NN + q0 + wid * 16 + g) * QKS;
        const uint32_t* ql = Ql + ((size_t)h * NN + q0 + wid * 16 + g) * QKS;
        #pragma unroll
        for (int ks = 0; ks < 4; ks++) {
            ah[ks][0] = qh[ks * 8 + t];       ah[ks][1] = qh[8 * QKS + ks * 8 + t];
            ah[ks][2] = qh[ks * 8 + t + 4];   ah[ks][3] = qh[8 * QKS + ks * 8 + t + 4];
            al[ks][0] = ql[ks * 8 + t];       al[ks][1] = ql[8 * QKS + ks * 8 + t];
            al[ks][2] = ql[ks * 8 + t + 4];   al[ks][3] = ql[8 * QKS + ks * 8 + t + 4];
        }
    }

    float o[8][4] = {};
    float m0 = -1e30f, m1 = -1e30f, l0 = 0.f, l1 = 0.f;

    for (int tt = 0; tt < NN / 64; tt++) {
        uint32_t* buf = sm + (tt & 1) * ATTN_BUF_U32;
        if (tt + 1 < NN / 64) {
            attn_stage(sm + ((tt + 1) & 1) * ATTN_BUF_U32, Kh, Vt, h, (tt + 1) * 64, tid);
            CP_COMMIT();
            CP_WAIT(1);
        } else {
            CP_WAIT(0);
        }
        __syncthreads();

        const uint32_t* kh = buf;
        const uint32_t* vs = buf + 2304;

        float s[8][4] = {};
        #pragma unroll
        for (int ks = 0; ks < 4; ks++) {
            #pragma unroll
            for (int nbp = 0; nbp < 4; nbp++) {
                uint32_t b[4];
                ldsm_x4(b, kh + boff + nbp * 576 + ks * 8);
                mma_f16(s[2 * nbp],     ah[ks], b);
                mma_f16(s[2 * nbp + 1], ah[ks], b + 2);
                mma_f16(s[2 * nbp],     al[ks], b);
                mma_f16(s[2 * nbp + 1], al[ks], b + 2);
            }
        }

        float mx0 = -1e30f, mx1 = -1e30f;
        #pragma unroll
        for (int nb = 0; nb < 8; nb++) {
            mx0 = fmaxf(mx0, fmaxf(s[nb][0], s[nb][1]));
            mx1 = fmaxf(mx1, fmaxf(s[nb][2], s[nb][3]));
        }
        mx0 = fmaxf(mx0, __shfl_xor_sync(0xffffffffu, mx0, 1));
        mx0 = fmaxf(mx0, __shfl_xor_sync(0xffffffffu, mx0, 2));
        mx1 = fmaxf(mx1, __shfl_xor_sync(0xffffffffu, mx1, 1));
        mx1 = fmaxf(mx1, __shfl_xor_sync(0xffffffffu, mx1, 2));

        float nm0 = fmaxf(m0, mx0), nm1 = fmaxf(m1, mx1);
        float sc0 = __expf(m0 - nm0), sc1 = __expf(m1 - nm1);
        float sum0 = 0.f, sum1 = 0.f;
        #pragma unroll
        for (int nb = 0; nb < 8; nb++) {
            s[nb][0] = __expf(s[nb][0] - nm0);
            s[nb][1] = __expf(s[nb][1] - nm0);
            s[nb][2] = __expf(s[nb][2] - nm1);
            s[nb][3] = __expf(s[nb][3] - nm1);
            sum0 += s[nb][0] + s[nb][1];
            sum1 += s[nb][2] + s[nb][3];
        }
        sum0 += __shfl_xor_sync(0xffffffffu, sum0, 1);
        sum0 += __shfl_xor_sync(0xffffffffu, sum0, 2);
        sum1 += __shfl_xor_sync(0xffffffffu, sum1, 1);
        sum1 += __shfl_xor_sync(0xffffffffu, sum1, 2);
        l0 = l0 * sc0 + sum0;  m0 = nm0;
        l1 = l1 * sc1 + sum1;  m1 = nm1;
        #pragma unroll
        for (int nb = 0; nb < 8; nb++) {
            o[nb][0] *= sc0; o[nb][1] *= sc0;
            o[nb][2] *= sc1; o[nb][3] *= sc1;
        }

        // O += P V (fp16)
        #pragma unroll
        for (int kp = 0; kp < 4; kp++) {
            uint32_t ap[4];
            ap[0] = pack2h(s[2 * kp][0],     s[2 * kp][1]);
            ap[1] = pack2h(s[2 * kp][2],     s[2 * kp][3]);
            ap[2] = pack2h(s[2 * kp + 1][0], s[2 * kp + 1][1]);
            ap[3] = pack2h(s[2 * kp + 1][2], s[2 * kp + 1][3]);
            #pragma unroll
            for (int nbp = 0; nbp < 4; nbp++) {
                uint32_t b[4];
                ldsm_x4(b, vs + boff + nbp * 576 + kp * 8);
                mma_f16(o[2 * nbp],     ap, b);
                mma_f16(o[2 * nbp + 1], ap, b + 2);
            }
        }
        __syncthreads();
    }

    // epilogue: write concat as single fp16 pairs
    const float inv0 = 1.0f / l0, inv1 = 1.0f / l1;
    const int r0 = q0 + wid * 16 + g;
    #pragma unroll
    for (int nb = 0; nb < 8; nb++) {
        int cpi = h * 32 + nb * 4 + t;
        Ch[(size_t)r0 * 512 + cpi]       = pack2h(o[nb][0] * inv0, o[nb][1] * inv0);
        Ch[(size_t)(r0 + 8) * 512 + cpi] = pack2h(o[nb][2] * inv1, o[nb][3] * inv1);
    }
}

// ---------------------------------------------------------------------------
// LayerNorm, one block per row
// ---------------------------------------------------------------------------
__global__ void __launch_bounds__(256) ln_kernel(const float* __restrict__ pre,
                                                 const float* __restrict__ alpha,
                                                 const float* __restrict__ beta,
                                                 float* __restrict__ out)
{
    const int row = blockIdx.x;
    const int tid = threadIdx.x;
    const float4 v = ((const float4*)(pre + (size_t)row * DM))[tid];

    float sum = v.x + v.y + v.z + v.w;
    float sq  = v.x * v.x + v.y * v.y + v.z * v.z + v.w * v.w;

    #pragma unroll
    for (int d = 16; d >= 1; d >>= 1) {
        sum += __shfl_xor_sync(0xffffffffu, sum, d);
        sq  += __shfl_xor_sync(0xffffffffu, sq,  d);
    }

    __shared__ float ssum[8], ssq[8];
    __shared__ float s_mu, s_rstd;
    int warp = tid >> 5, lane = tid & 31;
    if (lane == 0) { ssum[warp] = sum; ssq[warp] = sq; }
    __syncthreads();
    if (tid == 0) {
        float ts = 0.f, tq = 0.f;
        #pragma unroll
        for (int i = 0; i < 8; i++) { ts += ssum[i]; tq += ssq[i]; }
        float mu  = ts * (1.0f / DM);
        float var = tq * (1.0f / DM) - mu * mu;
        s_mu = mu;
        s_rstd = rsqrtf(var + LN_EPS);
    }
    __syncthreads();

    const float mu = s_mu, rstd = s_rstd;
    const float4 a4 = ((const float4*)alpha)[tid];
    const float4 b4 = ((const float4*)beta)[tid];
    float4 r;
    r.x = a4.x * (v.x - mu) * rstd + b4.x;
    r.y = a4.y * (v.y - mu) * rstd + b4.y;
    r.z = a4.z * (v.z - mu) * rstd + b4.z;
    r.w = a4.w * (v.w - mu) * rstd + b4.w;
    ((float4*)(out + (size_t)row * DM))[tid] = r;
}

// ---------------------------------------------------------------------------
extern "C" void kernel_launch(void* const* d_in, const int* in_sizes, int n_in,
                              void* d_out, int out_size)
{
    const float* x     = (const float*)d_in[0];
    const float* wq    = (const float*)d_in[1];
    const float* qb    = (const float*)d_in[2];
    const float* wk    = (const float*)d_in[3];
    const float* kb    = (const float*)d_in[4];
    const float* wv    = (const float*)d_in[5];
    const float* vb    = (const float*)d_in[6];
    const float* wo    = (const float*)d_in[7];
    const float* ob    = (const float*)d_in[8];
    const float* alpha = (const float*)d_in[9];
    const float* beta  = (const float*)d_in[10];
    float* out = (float*)d_out;

    uint32_t *Xh, *Xl, *Wq, *Wo;
    uint32_t *Qh, *Ql, *Kh, *Vt, *Ch;
    float *pre;
    cudaGetSymbolAddress((void**)&Xh,  g_Xh);
    cudaGetSymbolAddress((void**)&Xl,  g_Xl);
    cudaGetSymbolAddress((void**)&Wq,  g_Wq);
    cudaGetSymbolAddress((void**)&Wo,  g_Wo);
    cudaGetSymbolAddress((void**)&Qh,  g_Qh);
    cudaGetSymbolAddress((void**)&Ql,  g_Ql);
    cudaGetSymbolAddress((void**)&Kh,  g_Kh);
    cudaGetSymbolAddress((void**)&Vt,  g_Vt);
    cudaGetSymbolAddress((void**)&Ch,  g_Ch);
    cudaGetSymbolAddress((void**)&pre, g_pre);

    cudaFuncSetAttribute(qkv_kernel,
                         cudaFuncAttributeMaxDynamicSharedMemorySize, G_SMEM);
    cudaFuncSetAttribute(outproj_kernel,
                         cudaFuncAttributeMaxDynamicSharedMemorySize, G_SMEM);
    cudaFuncSetAttribute(attn_kernel,
                         cudaFuncAttributeMaxDynamicSharedMemorySize, ATTN_SMEM_BYTES);

    // conversions
    conv_x_kernel<<<NN, 256>>>(x, Xh, Xl);
    conv_wqkv_kernel<<<dim3(16, 1, 48), 256>>>(wq, wk, wv, Wq);
    conv_wo_kernel<<<dim3(16, 16, 1), 256>>>(wo, Wo);

    qkv_kernel<<<dim3(NN / 128, NH, 3), 256, G_SMEM>>>(Xh, Xl, Wq,
                                                       qb, kb, vb,
                                                       Qh, Ql, Kh, Vt);

    attn_kernel<<<dim3(NN / 128, NH), 256, ATTN_SMEM_BYTES>>>(Qh, Ql, Kh, Vt, Ch);

    outproj_kernel<<<dim3(NN / 128, DM / 64), 256, G_SMEM>>>(Ch, Wo,
                                                             x, ob, pre);

    ln_kernel<<<NN, 256>>>(pre, alpha, beta, out);
}

// round 13
// speedup vs baseline: 2.4556x; 1.1065x over previous
#include <cuda_runtime.h>
#include <cuda_fp16.h>
#include <cstdint>

#define NN 2048
#define DM 1024
#define NH 16
#define DK 64
#define LN_EPS 1e-5f
#define QKS 36   // u32 row stride for packed Q/K (32 pairs + 4 pad)

// Scratch (device globals) — fp16 pair arrays (u32 = f16x2)
__device__ uint32_t g_Xh[(size_t)NN * 512];
__device__ uint32_t g_Wq[(size_t)NH * 192 * 512];     // single fp16
__device__ uint32_t g_Wo[(size_t)DM * 512];           // single fp16
__device__ uint32_t g_Qh[(size_t)NH * NN * QKS];
__device__ uint32_t g_Ql[(size_t)NH * NN * QKS];
__device__ uint32_t g_Kh[(size_t)NH * NN * QKS];      // single fp16
__device__ uint32_t g_Vt[(size_t)NH * DK * (NN / 2)]; // fp16 [h][dk][keypair]
__device__ uint32_t g_Ch[(size_t)NN * 512];           // concat, single fp16
__device__ float    g_pre[(size_t)NN * DM];

// ---------------------------------------------------------------------------
// helpers
// ---------------------------------------------------------------------------
__device__ __forceinline__ uint32_t pack2h(float e0, float e1) {  // f16x2: e0 low
    uint32_t r;
    asm("cvt.rn.f16x2.f32 %0, %1, %2;" : "=r"(r) : "f"(e1), "f"(e0));
    return r;
}
__device__ __forceinline__ uint16_t f16bits(float v) {
    uint16_t u;
    asm("cvt.rn.f16.f32 %0, %1;" : "=h"(u) : "f"(v));
    return u;
}
// split pair (x0,x1) into hi-f16x2 + lo-f16x2 residual
__device__ __forceinline__ void split2h(float x0, float x1, uint32_t& hi, uint32_t& lo) {
    __half2 h = __floats2half2_rn(x0, x1);
    float2 hf = __half22float2(h);
    __half2 l = __floats2half2_rn(x0 - hf.x, x1 - hf.y);
    hi = *(uint32_t*)&h;
    lo = *(uint32_t*)&l;
}
__device__ __forceinline__ void mma_f16(float* c, const uint32_t* a, const uint32_t* b) {
    asm("mma.sync.aligned.m16n8k16.row.col.f32.f16.f16.f32 "
        "{%0,%1,%2,%3}, {%4,%5,%6,%7}, {%8,%9}, {%0,%1,%2,%3};\n"
        : "+f"(c[0]), "+f"(c[1]), "+f"(c[2]), "+f"(c[3])
        : "r"(a[0]), "r"(a[1]), "r"(a[2]), "r"(a[3]), "r"(b[0]), "r"(b[1]));
}
__device__ __forceinline__ void ldsm_x4(uint32_t* r, const uint32_t* p) {
    uint32_t addr = (uint32_t)__cvta_generic_to_shared(p);
    asm volatile("ldmatrix.sync.aligned.m8n8.x4.shared.b16 {%0,%1,%2,%3}, [%4];"
        : "=r"(r[0]), "=r"(r[1]), "=r"(r[2]), "=r"(r[3]) : "r"(addr));
}
#define CPA16(sptr, gptr) do {                                                 \
    uint32_t _s = (uint32_t)__cvta_generic_to_shared(sptr);                    \
    asm volatile("cp.async.cg.shared.global [%0], [%1], 16;" :: "r"(_s), "l"(gptr)); \
} while (0)
#define CP_COMMIT() asm volatile("cp.async.commit_group;")
#define CP_WAIT(n)  asm volatile("cp.async.wait_group %0;" :: "n"(n))

// ---------------------------------------------------------------------------
// conversion kernels
// ---------------------------------------------------------------------------
__global__ void __launch_bounds__(256) conv_x_kernel(const float* __restrict__ x,
                                                     uint32_t* __restrict__ Xh)
{
    const int r = blockIdx.x, t = threadIdx.x;
    float4 v = ((const float4*)x)[r * 256 + t];
    Xh[(size_t)r * 512 + 2 * t]     = pack2h(v.x, v.y);
    Xh[(size_t)r * 512 + 2 * t + 1] = pack2h(v.z, v.w);
}

// fused wq/wk/wv: single fp16, [h][sec*64+n][kpair], row stride 512 u32
__global__ void __launch_bounds__(256) conv_wqkv_kernel(const float* __restrict__ wq,
                                                        const float* __restrict__ wk,
                                                        const float* __restrict__ wv,
                                                        uint32_t* __restrict__ dst)
{
    __shared__ float sw[64][65];
    const int k0 = blockIdx.x * 64;
    const int z  = blockIdx.z;
    const int sec = z >> 4, h = z & 15;
    const int t  = threadIdx.x;
    const float* s = (sec == 0 ? wq : sec == 1 ? wk : wv) + (size_t)h * DM * DK;

    #pragma unroll
    for (int i = 0; i < 16; i++) {
        int idx = i * 256 + t;
        int row = idx >> 6, col = idx & 63;
        sw[row][col] = s[(size_t)(k0 + row) * DK + col];
    }
    __syncthreads();
    #pragma unroll
    for (int i = 0; i < 8; i++) {
        int idx = i * 256 + t;
        int n = idx >> 5, kp = idx & 31;
        size_t o = (size_t)h * (192 * 512) + (size_t)(sec * 64 + n) * 512 + k0 / 2 + kp;
        dst[o] = pack2h(sw[2 * kp][n], sw[2 * kp + 1][n]);
    }
}

__global__ void __launch_bounds__(256) conv_wo_kernel(const float* __restrict__ src,
                                                      uint32_t* __restrict__ dst)
{
    __shared__ float sw[64][65];
    const int k0 = blockIdx.x * 64;
    const int n0 = blockIdx.y * 64;
    const int t  = threadIdx.x;

    #pragma unroll
    for (int i = 0; i < 16; i++) {
        int idx = i * 256 + t;
        int row = idx >> 6, col = idx & 63;
        sw[row][col] = src[(size_t)(k0 + row) * DM + n0 + col];
    }
    __syncthreads();
    #pragma unroll
    for (int i = 0; i < 8; i++) {
        int idx = i * 256 + t;
        int n = idx >> 5, kp = idx & 31;
        size_t o = (size_t)(n0 + n) * 512 + k0 / 2 + kp;
        dst[o] = pack2h(sw[2 * kp][n], sw[2 * kp + 1][n]);
    }
}

// ---------------------------------------------------------------------------
// GEMM tile machinery: 128 rows x 64 cols, k-chunk 32, 2-stage cp.async.
// Single-term fp16: A single, B single. LDSM loads.
// Stage = A(2560) + B(1280) = 3840 u32; 2 stages = 30720 B.
// ---------------------------------------------------------------------------
#define G_STAGE_U32 3840
#define G_SMEM (2 * G_STAGE_U32 * 4)

__device__ __forceinline__ void gemm_stage_load(uint32_t* st,
                                                const uint32_t* Ag, const uint32_t* Bg,
                                                int kc16, int tid)
{
    #pragma unroll
    for (int i = 0; i < 2; i++) {
        int idx = tid + i * 256;               // 0..511
        int row = idx >> 2, sg = (idx & 3) * 4;
        CPA16(st + row * 20 + sg, Ag + (size_t)row * 512 + kc16 + sg);
    }
    {
        int row = tid >> 2, sg = (tid & 3) * 4;  // rows 0..63
        CPA16(st + 2560 + row * 20 + sg, Bg + (size_t)row * 512 + kc16 + sg);
    }
}

__device__ __forceinline__ void gemm_core(uint32_t* sm, float (*acc)[4],
                                          const uint32_t* Ag, const uint32_t* Bg,
                                          int tid, int aoff, int boff)
{
    gemm_stage_load(sm, Ag, Bg, 0, tid);
    CP_COMMIT();

    for (int c = 0; c < 32; c++) {
        if (c < 31) {
            gemm_stage_load(sm + ((c + 1) & 1) * G_STAGE_U32,
                            Ag, Bg, (c + 1) * 16, tid);
            CP_COMMIT();
            CP_WAIT(1);
        } else {
            CP_WAIT(0);
        }
        __syncthreads();

        const uint32_t* p  = sm + (c & 1) * G_STAGE_U32;
        const uint32_t* As = p;
        const uint32_t* Bs = p + 2560;

        #pragma unroll
        for (int ks = 0; ks < 2; ks++) {
            uint32_t a[4];
            ldsm_x4(a, As + aoff + ks * 8);
            #pragma unroll
            for (int nbp = 0; nbp < 4; nbp++) {
                uint32_t b[4];
                ldsm_x4(b, Bs + boff + nbp * 320 + ks * 8);
                mma_f16(acc[2 * nbp],     a, b);
                mma_f16(acc[2 * nbp + 1], a, b + 2);
            }
        }
        __syncthreads();
    }
}

// ---------------------------------------------------------------------------
// QKV GEMM: CTA = (row-tile, head, section). section: 0=Q, 1=K, 2=V.
// All single-term fp16. Q stores split (preserves GEMM value for attn 2-term).
// ---------------------------------------------------------------------------
__global__ void __launch_bounds__(256, 3) qkv_kernel(const uint32_t* __restrict__ Xh,
                                                     const uint32_t* __restrict__ W,
                                                     const float* __restrict__ qb,
                                                     const float* __restrict__ kb,
                                                     const float* __restrict__ vb,
                                                     uint32_t* __restrict__ oQh,
                                                     uint32_t* __restrict__ oQl,
                                                     uint32_t* __restrict__ oKh,
                                                     uint32_t* __restrict__ oVt)
{
    extern __shared__ uint32_t sm[];
    const int m0  = blockIdx.x * 128;
    const int h   = blockIdx.y;
    const int sec = blockIdx.z;
    const int tid = threadIdx.x;
    const int wid = tid >> 5, lane = tid & 31, g = lane >> 2, t = lane & 3;
    const int lrow = lane & 7;
    const int aoff = (wid * 16 + lrow + ((lane >> 3) & 1) * 8) * 20 + (lane >> 4) * 4;
    const int boff = (lrow + ((lane >> 4) & 1) * 8) * 20 + ((lane >> 3) & 1) * 4;

    float acc[8][4] = {};

    gemm_core(sm, acc,
              Xh + (size_t)m0 * 512,
              W + ((size_t)h * 192 + sec * 64) * 512,
              tid, aoff, boff);

    const int r = wid * 16 + g;
    const int grow = m0 + r;

    if (sec == 0) {
        // Q: split fp16, pre-scaled 0.125
        #pragma unroll
        for (int nb = 0; nb < 8; nb++) {
            int col = nb * 8 + 2 * t;
            float b0 = qb[h * DK + col], b1 = qb[h * DK + col + 1];
            uint32_t h0, l0, h1, l1;
            split2h((acc[nb][0] + b0) * 0.125f, (acc[nb][1] + b1) * 0.125f, h0, l0);
            split2h((acc[nb][2] + b0) * 0.125f, (acc[nb][3] + b1) * 0.125f, h1, l1);
            size_t base = ((size_t)h * NN + grow) * QKS + nb * 4 + t;
            oQh[base] = h0;            oQl[base] = l0;
            oQh[base + 8 * QKS] = h1;  oQl[base + 8 * QKS] = l1;
        }
    } else if (sec == 1) {
        // K: single fp16
        #pragma unroll
        for (int nb = 0; nb < 8; nb++) {
            int col = nb * 8 + 2 * t;
            float b0 = kb[h * DK + col], b1 = kb[h * DK + col + 1];
            size_t base = ((size_t)h * NN + grow) * QKS + nb * 4 + t;
            oKh[base]           = pack2h(acc[nb][0] + b0, acc[nb][1] + b1);
            oKh[base + 8 * QKS] = pack2h(acc[nb][2] + b0, acc[nb][3] + b1);
        }
    } else {
        // V: fp16 transpose via smem ([64 dk][132 fp16] = stride 66 u32)
        uint16_t* Vs16 = (uint16_t*)sm;
        #pragma unroll
        for (int nb = 0; nb < 8; nb++) {
            int col = nb * 8 + 2 * t;
            float b0 = vb[h * DK + col], b1 = vb[h * DK + col + 1];
            Vs16[(col)     * 132 + r]     = f16bits(acc[nb][0] + b0);
            Vs16[(col + 1) * 132 + r]     = f16bits(acc[nb][1] + b1);
            Vs16[(col)     * 132 + r + 8] = f16bits(acc[nb][2] + b0);
            Vs16[(col + 1) * 132 + r + 8] = f16bits(acc[nb][3] + b1);
        }
        __syncthreads();
        #pragma unroll
        for (int i = 0; i < 16; i++) {
            int idx = tid + i * 256;
            int dk = idx >> 6, cc = idx & 63;
            oVt[((size_t)h * DK + dk) * (NN / 2) + m0 / 2 + cc] = sm[dk * 66 + cc];
        }
    }
}

// ---------------------------------------------------------------------------
// Out projection + bias + residual: CTA = (row-tile, 64-col tile). 1-term.
// ---------------------------------------------------------------------------
__global__ void __launch_bounds__(256, 3) outproj_kernel(const uint32_t* __restrict__ Ag,
                                                         const uint32_t* __restrict__ Bg,
                                                         const float* __restrict__ x,
                                                         const float* __restrict__ ob,
                                                         float* __restrict__ out)
{
    extern __shared__ uint32_t sm[];
    const int m0 = blockIdx.x * 128;
    const int c0 = blockIdx.y * 64;
    const int tid = threadIdx.x;
    const int wid = tid >> 5, lane = tid & 31, g = lane >> 2, t = lane & 3;
    const int lrow = lane & 7;
    const int aoff = (wid * 16 + lrow + ((lane >> 3) & 1) * 8) * 20 + (lane >> 4) * 4;
    const int boff = (lrow + ((lane >> 4) & 1) * 8) * 20 + ((lane >> 3) & 1) * 4;

    float acc[8][4] = {};

    gemm_core(sm, acc,
              Ag + (size_t)m0 * 512,
              Bg + (size_t)c0 * 512,
              tid, aoff, boff);

    const int r0 = m0 + wid * 16 + g;
    #pragma unroll
    for (int nb = 0; nb < 8; nb++) {
        int col = c0 + nb * 8 + 2 * t;
        float b0 = ob[col], b1 = ob[col + 1];
        const float* xr0 = &x[(size_t)r0 * DM + col];
        const float* xr1 = &x[(size_t)(r0 + 8) * DM + col];
        float2 v0 = make_float2(acc[nb][0] + b0 + xr0[0], acc[nb][1] + b1 + xr0[1]);
        float2 v1 = make_float2(acc[nb][2] + b0 + xr1[0], acc[nb][3] + b1 + xr1[1]);
        *(float2*)&out[(size_t)r0 * DM + col]       = v0;
        *(float2*)&out[(size_t)(r0 + 8) * DM + col] = v1;
    }
}

// ---------------------------------------------------------------------------
// Flash attention: fp16 QK (2-term, Q split / K single, B-frag reused) + fp16 PV.
// buf = Kh[64][36] + Vt[64][36] = 4608 u32 per stage.
// ---------------------------------------------------------------------------
#define ATTN_BUF_U32 (2 * 64 * 36)
#define ATTN_SMEM_BYTES (2 * ATTN_BUF_U32 * 4)

__device__ __forceinline__ void attn_stage(uint32_t* dst, const uint32_t* Kh,
                                           const uint32_t* Vt,
                                           int h, int t0, int tid)
{
    const uint32_t* sKh = Kh + ((size_t)h * NN + t0) * QKS;
    const uint32_t* sVt = Vt + (size_t)h * DK * (NN / 2) + t0 / 2;
    for (int idx = tid; idx < 1088; idx += 256) {
        if (idx < 576) {
            CPA16(dst + idx * 4, sKh + idx * 4);
        } else {
            int j = idx - 576;
            int dk = j >> 3, c = (j & 7) * 4;
            CPA16(dst + 2304 + dk * 36 + c, sVt + (size_t)dk * (NN / 2) + c);
        }
    }
}

__global__ void __launch_bounds__(256, 2) attn_kernel(const uint32_t* __restrict__ Qh,
                                                      const uint32_t* __restrict__ Ql,
                                                      const uint32_t* __restrict__ Kh,
                                                      const uint32_t* __restrict__ Vt,
                                                      uint32_t* __restrict__ Ch)
{
    extern __shared__ uint32_t sm[];
    const int h  = blockIdx.y;
    const int q0 = blockIdx.x * 128;
    const int tid = threadIdx.x;
    const int wid = tid >> 5, lane = tid & 31, g = lane >> 2, t = lane & 3;
    const int lrow = lane & 7;
    const int boff = (lrow + ((lane >> 4) & 1) * 8) * 36 + ((lane >> 3) & 1) * 4;

    attn_stage(sm, Kh, Vt, h, 0, tid);
    CP_COMMIT();

    uint32_t ah[4][4], al[4][4];
    {
        const uint32_t* qh = Qh + ((size_t)h * NN + q0 + wid * 16 + g) * QKS;
        const uint32_t* ql = Ql + ((size_t)h * NN + q0 + wid * 16 + g) * QKS;
        #pragma unroll
        for (int ks = 0; ks < 4; ks++) {
            ah[ks][0] = qh[ks * 8 + t];       ah[ks][1] = qh[8 * QKS + ks * 8 + t];
            ah[ks][2] = qh[ks * 8 + t + 4];   ah[ks][3] = qh[8 * QKS + ks * 8 + t + 4];
            al[ks][0] = ql[ks * 8 + t];       al[ks][1] = ql[8 * QKS + ks * 8 + t];
            al[ks][2] = ql[ks * 8 + t + 4];   al[ks][3] = ql[8 * QKS + ks * 8 + t + 4];
        }
    }

    float o[8][4] = {};
    float m0 = -1e30f, m1 = -1e30f, l0 = 0.f, l1 = 0.f;

    for (int tt = 0; tt < NN / 64; tt++) {
        uint32_t* buf = sm + (tt & 1) * ATTN_BUF_U32;
        if (tt + 1 < NN / 64) {
            attn_stage(sm + ((tt + 1) & 1) * ATTN_BUF_U32, Kh, Vt, h, (tt + 1) * 64, tid);
            CP_COMMIT();
            CP_WAIT(1);
        } else {
            CP_WAIT(0);
        }
        __syncthreads();

        const uint32_t* kh = buf;
        const uint32_t* vs = buf + 2304;

        float s[8][4] = {};
        #pragma unroll
        for (int ks = 0; ks < 4; ks++) {
            #pragma unroll
            for (int nbp = 0; nbp < 4; nbp++) {
                uint32_t b[4];
                ldsm_x4(b, kh + boff + nbp * 576 + ks * 8);
                mma_f16(s[2 * nbp],     ah[ks], b);
                mma_f16(s[2 * nbp + 1], ah[ks], b + 2);
                mma_f16(s[2 * nbp],     al[ks], b);
                mma_f16(s[2 * nbp + 1], al[ks], b + 2);
            }
        }

        float mx0 = -1e30f, mx1 = -1e30f;
        #pragma unroll
        for (int nb = 0; nb < 8; nb++) {
            mx0 = fmaxf(mx0, fmaxf(s[nb][0], s[nb][1]));
            mx1 = fmaxf(mx1, fmaxf(s[nb][2], s[nb][3]));
        }
        mx0 = fmaxf(mx0, __shfl_xor_sync(0xffffffffu, mx0, 1));
        mx0 = fmaxf(mx0, __shfl_xor_sync(0xffffffffu, mx0, 2));
        mx1 = fmaxf(mx1, __shfl_xor_sync(0xffffffffu, mx1, 1));
        mx1 = fmaxf(mx1, __shfl_xor_sync(0xffffffffu, mx1, 2));

        float nm0 = fmaxf(m0, mx0), nm1 = fmaxf(m1, mx1);
        float sc0 = __expf(m0 - nm0), sc1 = __expf(m1 - nm1);
        float sum0 = 0.f, sum1 = 0.f;
        #pragma unroll
        for (int nb = 0; nb < 8; nb++) {
            s[nb][0] = __expf(s[nb][0] - nm0);
            s[nb][1] = __expf(s[nb][1] - nm0);
            s[nb][2] = __expf(s[nb][2] - nm1);
            s[nb][3] = __expf(s[nb][3] - nm1);
            sum0 += s[nb][0] + s[nb][1];
            sum1 += s[nb][2] + s[nb][3];
        }
        sum0 += __shfl_xor_sync(0xffffffffu, sum0, 1);
        sum0 += __shfl_xor_sync(0xffffffffu, sum0, 2);
        sum1 += __shfl_xor_sync(0xffffffffu, sum1, 1);
        sum1 += __shfl_xor_sync(0xffffffffu, sum1, 2);
        l0 = l0 * sc0 + sum0;  m0 = nm0;
        l1 = l1 * sc1 + sum1;  m1 = nm1;
        #pragma unroll
        for (int nb = 0; nb < 8; nb++) {
            o[nb][0] *= sc0; o[nb][1] *= sc0;
            o[nb][2] *= sc1; o[nb][3] *= sc1;
        }

        // O += P V (fp16)
        #pragma unroll
        for (int kp = 0; kp < 4; kp++) {
            uint32_t ap[4];
            ap[0] = pack2h(s[2 * kp][0],     s[2 * kp][1]);
            ap[1] = pack2h(s[2 * kp][2],     s[2 * kp][3]);
            ap[2] = pack2h(s[2 * kp + 1][0], s[2 * kp + 1][1]);
            ap[3] = pack2h(s[2 * kp + 1][2], s[2 * kp + 1][3]);
            #pragma unroll
            for (int nbp = 0; nbp < 4; nbp++) {
                uint32_t b[4];
                ldsm_x4(b, vs + boff + nbp * 576 + kp * 8);
                mma_f16(o[2 * nbp],     ap, b);
                mma_f16(o[2 * nbp + 1], ap, b + 2);
            }
        }
        __syncthreads();
    }

    // epilogue: write concat as single fp16 pairs
    const float inv0 = 1.0f / l0, inv1 = 1.0f / l1;
    const int r0 = q0 + wid * 16 + g;
    #pragma unroll
    for (int nb = 0; nb < 8; nb++) {
        int cpi = h * 32 + nb * 4 + t;
        Ch[(size_t)r0 * 512 + cpi]       = pack2h(o[nb][0] * inv0, o[nb][1] * inv0);
        Ch[(size_t)(r0 + 8) * 512 + cpi] = pack2h(o[nb][2] * inv1, o[nb][3] * inv1);
    }
}

// ---------------------------------------------------------------------------
// LayerNorm, one block per row
// ---------------------------------------------------------------------------
__global__ void __launch_bounds__(256) ln_kernel(const float* __restrict__ pre,
                                                 const float* __restrict__ alpha,
                                                 const float* __restrict__ beta,
                                                 float* __restrict__ out)
{
    const int row = blockIdx.x;
    const int tid = threadIdx.x;
    const float4 v = ((const float4*)(pre + (size_t)row * DM))[tid];

    float sum = v.x + v.y + v.z + v.w;
    float sq  = v.x * v.x + v.y * v.y + v.z * v.z + v.w * v.w;

    #pragma unroll
    for (int d = 16; d >= 1; d >>= 1) {
        sum += __shfl_xor_sync(0xffffffffu, sum, d);
        sq  += __shfl_xor_sync(0xffffffffu, sq,  d);
    }

    __shared__ float ssum[8], ssq[8];
    __shared__ float s_mu, s_rstd;
    int warp = tid >> 5, lane = tid & 31;
    if (lane == 0) { ssum[warp] = sum; ssq[warp] = sq; }
    __syncthreads();
    if (tid == 0) {
        float ts = 0.f, tq = 0.f;
        #pragma unroll
        for (int i = 0; i < 8; i++) { ts += ssum[i]; tq += ssq[i]; }
        float mu  = ts * (1.0f / DM);
        float var = tq * (1.0f / DM) - mu * mu;
        s_mu = mu;
        s_rstd = rsqrtf(var + LN_EPS);
    }
    __syncthreads();

    const float mu = s_mu, rstd = s_rstd;
    const float4 a4 = ((const float4*)alpha)[tid];
    const float4 b4 = ((const float4*)beta)[tid];
    float4 r;
    r.x = a4.x * (v.x - mu) * rstd + b4.x;
    r.y = a4.y * (v.y - mu) * rstd + b4.y;
    r.z = a4.z * (v.z - mu) * rstd + b4.z;
    r.w = a4.w * (v.w - mu) * rstd + b4.w;
    ((float4*)(out + (size_t)row * DM))[tid] = r;
}

// ---------------------------------------------------------------------------
extern "C" void kernel_launch(void* const* d_in, const int* in_sizes, int n_in,
                              void* d_out, int out_size)
{
    const float* x     = (const float*)d_in[0];
    const float* wq    = (const float*)d_in[1];
    const float* qb    = (const float*)d_in[2];
    const float* wk    = (const float*)d_in[3];
    const float* kb    = (const float*)d_in[4];
    const float* wv    = (const float*)d_in[5];
    const float* vb    = (const float*)d_in[6];
    const float* wo    = (const float*)d_in[7];
    const float* ob    = (const float*)d_in[8];
    const float* alpha = (const float*)d_in[9];
    const float* beta  = (const float*)d_in[10];
    float* out = (float*)d_out;

    uint32_t *Xh, *Wq, *Wo;
    uint32_t *Qh, *Ql, *Kh, *Vt, *Ch;
    float *pre;
    cudaGetSymbolAddress((void**)&Xh,  g_Xh);
    cudaGetSymbolAddress((void**)&Wq,  g_Wq);
    cudaGetSymbolAddress((void**)&Wo,  g_Wo);
    cudaGetSymbolAddress((void**)&Qh,  g_Qh);
    cudaGetSymbolAddress((void**)&Ql,  g_Ql);
    cudaGetSymbolAddress((void**)&Kh,  g_Kh);
    cudaGetSymbolAddress((void**)&Vt,  g_Vt);
    cudaGetSymbolAddress((void**)&Ch,  g_Ch);
    cudaGetSymbolAddress((void**)&pre, g_pre);

    cudaFuncSetAttribute(qkv_kernel,
                         cudaFuncAttributeMaxDynamicSharedMemorySize, G_SMEM);
    cudaFuncSetAttribute(outproj_kernel,
                         cudaFuncAttributeMaxDynamicSharedMemorySize, G_SMEM);
    cudaFuncSetAttribute(attn_kernel,
                         cudaFuncAttributeMaxDynamicSharedMemorySize, ATTN_SMEM_BYTES);

    // conversions
    conv_x_kernel<<<NN, 256>>>(x, Xh);
    conv_wqkv_kernel<<<dim3(16, 1, 48), 256>>>(wq, wk, wv, Wq);
    conv_wo_kernel<<<dim3(16, 16, 1), 256>>>(wo, Wo);

    qkv_kernel<<<dim3(NN / 128, NH, 3), 256, G_SMEM>>>(Xh, Wq,
                                                       qb, kb, vb,
                                                       Qh, Ql, Kh, Vt);

    attn_kernel<<<dim3(NN / 128, NH), 256, ATTN_SMEM_BYTES>>>(Qh, Ql, Kh, Vt, Ch);

    outproj_kernel<<<dim3(NN / 128, DM / 64), 256, G_SMEM>>>(Ch, Wo,
                                                             x, ob, pre);

    ln_kernel<<<NN, 256>>>(pre, alpha, beta, out);
}

// round 14
// speedup vs baseline: 2.9640x; 1.2070x over previous
#include <cuda_runtime.h>
#include <cuda_fp16.h>
#include <cstdint>

#define NN 2048
#define DM 1024
#define NH 16
#define DK 64
#define LN_EPS 1e-5f
#define QKS 36   // u32 row stride for packed Q/K (32 pairs + 4 pad)

// Scratch (device globals) — fp16 pair arrays (u32 = f16x2)
__device__ uint32_t g_Xh[(size_t)NN * 512];
__device__ uint32_t g_Wq[(size_t)NH * 192 * 512];     // single fp16
__device__ uint32_t g_Wo[(size_t)DM * 512];           // single fp16
__device__ uint32_t g_Qh[(size_t)NH * NN * QKS];      // single fp16 (pre-scaled)
__device__ uint32_t g_Kh[(size_t)NH * NN * QKS];      // single fp16
__device__ uint32_t g_Vt[(size_t)NH * DK * (NN / 2)]; // fp16 [h][dk][keypair]
__device__ uint32_t g_Ch[(size_t)NN * 512];           // concat, single fp16
__device__ float    g_pre[(size_t)NN * DM];

// ---------------------------------------------------------------------------
// helpers
// ---------------------------------------------------------------------------
__device__ __forceinline__ uint32_t pack2h(float e0, float e1) {  // f16x2: e0 low
    uint32_t r;
    asm("cvt.rn.f16x2.f32 %0, %1, %2;" : "=r"(r) : "f"(e1), "f"(e0));
    return r;
}
__device__ __forceinline__ uint16_t f16bits(float v) {
    uint16_t u;
    asm("cvt.rn.f16.f32 %0, %1;" : "=h"(u) : "f"(v));
    return u;
}
__device__ __forceinline__ void mma_f16(float* c, const uint32_t* a, const uint32_t* b) {
    asm("mma.sync.aligned.m16n8k16.row.col.f32.f16.f16.f32 "
        "{%0,%1,%2,%3}, {%4,%5,%6,%7}, {%8,%9}, {%0,%1,%2,%3};\n"
        : "+f"(c[0]), "+f"(c[1]), "+f"(c[2]), "+f"(c[3])
        : "r"(a[0]), "r"(a[1]), "r"(a[2]), "r"(a[3]), "r"(b[0]), "r"(b[1]));
}
__device__ __forceinline__ void ldsm_x4(uint32_t* r, const uint32_t* p) {
    uint32_t addr = (uint32_t)__cvta_generic_to_shared(p);
    asm volatile("ldmatrix.sync.aligned.m8n8.x4.shared.b16 {%0,%1,%2,%3}, [%4];"
        : "=r"(r[0]), "=r"(r[1]), "=r"(r[2]), "=r"(r[3]) : "r"(addr));
}
#define CPA16(sptr, gptr) do {                                                 \
    uint32_t _s = (uint32_t)__cvta_generic_to_shared(sptr);                    \
    asm volatile("cp.async.cg.shared.global [%0], [%1], 16;" :: "r"(_s), "l"(gptr)); \
} while (0)
#define CP_COMMIT() asm volatile("cp.async.commit_group;")
#define CP_WAIT(n)  asm volatile("cp.async.wait_group %0;" :: "n"(n))

// ---------------------------------------------------------------------------
// conversion kernels
// ---------------------------------------------------------------------------
__global__ void __launch_bounds__(256) conv_x_kernel(const float* __restrict__ x,
                                                     uint32_t* __restrict__ Xh)
{
    const int r = blockIdx.x, t = threadIdx.x;
    float4 v = ((const float4*)x)[r * 256 + t];
    Xh[(size_t)r * 512 + 2 * t]     = pack2h(v.x, v.y);
    Xh[(size_t)r * 512 + 2 * t + 1] = pack2h(v.z, v.w);
}

// fused wq/wk/wv: single fp16, [h][sec*64+n][kpair], row stride 512 u32
__global__ void __launch_bounds__(256) conv_wqkv_kernel(const float* __restrict__ wq,
                                                        const float* __restrict__ wk,
                                                        const float* __restrict__ wv,
                                                        uint32_t* __restrict__ dst)
{
    __shared__ float sw[64][65];
    const int k0 = blockIdx.x * 64;
    const int z  = blockIdx.z;
    const int sec = z >> 4, h = z & 15;
    const int t  = threadIdx.x;
    const float* s = (sec == 0 ? wq : sec == 1 ? wk : wv) + (size_t)h * DM * DK;

    #pragma unroll
    for (int i = 0; i < 16; i++) {
        int idx = i * 256 + t;
        int row = idx >> 6, col = idx & 63;
        sw[row][col] = s[(size_t)(k0 + row) * DK + col];
    }
    __syncthreads();
    #pragma unroll
    for (int i = 0; i < 8; i++) {
        int idx = i * 256 + t;
        int n = idx >> 5, kp = idx & 31;
        size_t o = (size_t)h * (192 * 512) + (size_t)(sec * 64 + n) * 512 + k0 / 2 + kp;
        dst[o] = pack2h(sw[2 * kp][n], sw[2 * kp + 1][n]);
    }
}

__global__ void __launch_bounds__(256) conv_wo_kernel(const float* __restrict__ src,
                                                      uint32_t* __restrict__ dst)
{
    __shared__ float sw[64][65];
    const int k0 = blockIdx.x * 64;
    const int n0 = blockIdx.y * 64;
    const int t  = threadIdx.x;

    #pragma unroll
    for (int i = 0; i < 16; i++) {
        int idx = i * 256 + t;
        int row = idx >> 6, col = idx & 63;
        sw[row][col] = src[(size_t)(k0 + row) * DM + n0 + col];
    }
    __syncthreads();
    #pragma unroll
    for (int i = 0; i < 8; i++) {
        int idx = i * 256 + t;
        int n = idx >> 5, kp = idx & 31;
        size_t o = (size_t)(n0 + n) * 512 + k0 / 2 + kp;
        dst[o] = pack2h(sw[2 * kp][n], sw[2 * kp + 1][n]);
    }
}

// ---------------------------------------------------------------------------
// GEMM tile machinery: 128 rows x 64 cols, k-chunk 64, 2-stage cp.async.
// Single-term fp16. Rows stored stride-36 u32 (32 data + 4 pad), matching
// the attention kernel's proven layout.
// Stage = A(128*36) + B(64*36) = 6912 u32; 2 stages = 55296 B.
// ---------------------------------------------------------------------------
#define G_STAGE_U32 6912
#define G_SMEM (2 * G_STAGE_U32 * 4)

__device__ __forceinline__ void gemm_stage_load(uint32_t* st,
                                                const uint32_t* Ag, const uint32_t* Bg,
                                                int kc32, int tid)
{
    #pragma unroll
    for (int i = 0; i < 4; i++) {
        int idx = tid + i * 256;               // 0..1023 : A rows 0..127
        int row = idx >> 3, blk = idx & 7;
        CPA16(st + row * 36 + blk * 4, Ag + (size_t)row * 512 + kc32 + blk * 4);
    }
    #pragma unroll
    for (int i = 0; i < 2; i++) {
        int idx = tid + i * 256;               // 0..511 : B rows 0..63
        int row = idx >> 3, blk = idx & 7;
        CPA16(st + 4608 + row * 36 + blk * 4, Bg + (size_t)row * 512 + kc32 + blk * 4);
    }
}

__device__ __forceinline__ void gemm_core(uint32_t* sm, float (*acc)[4],
                                          const uint32_t* Ag, const uint32_t* Bg,
                                          int tid, int aoff, int boff)
{
    gemm_stage_load(sm, Ag, Bg, 0, tid);
    CP_COMMIT();

    for (int c = 0; c < 16; c++) {
        if (c < 15) {
            gemm_stage_load(sm + ((c + 1) & 1) * G_STAGE_U32,
                            Ag, Bg, (c + 1) * 32, tid);
            CP_COMMIT();
            CP_WAIT(1);
        } else {
            CP_WAIT(0);
        }
        __syncthreads();

        const uint32_t* p  = sm + (c & 1) * G_STAGE_U32;
        const uint32_t* As = p;
        const uint32_t* Bs = p + 4608;

        #pragma unroll
        for (int ks = 0; ks < 4; ks++) {
            uint32_t a[4];
            ldsm_x4(a, As + aoff + ks * 8);
            #pragma unroll
            for (int nbp = 0; nbp < 4; nbp++) {
                uint32_t b[4];
                ldsm_x4(b, Bs + boff + nbp * 576 + ks * 8);
                mma_f16(acc[2 * nbp],     a, b);
                mma_f16(acc[2 * nbp + 1], a, b + 2);
            }
        }
        __syncthreads();
    }
}

// ---------------------------------------------------------------------------
// QKV GEMM: CTA = (row-tile, head, section). section: 0=Q, 1=K, 2=V.
// All single-term fp16; Q stored single fp16 (pre-scaled 0.125).
// ---------------------------------------------------------------------------
__global__ void __launch_bounds__(256, 3) qkv_kernel(const uint32_t* __restrict__ Xh,
                                                     const uint32_t* __restrict__ W,
                                                     const float* __restrict__ qb,
                                                     const float* __restrict__ kb,
                                                     const float* __restrict__ vb,
                                                     uint32_t* __restrict__ oQh,
                                                     uint32_t* __restrict__ oKh,
                                                     uint32_t* __restrict__ oVt)
{
    extern __shared__ uint32_t sm[];
    const int m0  = blockIdx.x * 128;
    const int h   = blockIdx.y;
    const int sec = blockIdx.z;
    const int tid = threadIdx.x;
    const int wid = tid >> 5, lane = tid & 31, g = lane >> 2, t = lane & 3;
    const int lrow = lane & 7;
    const int aoff = (wid * 16 + lrow + ((lane >> 3) & 1) * 8) * 36 + (lane >> 4) * 4;
    const int boff = (lrow + ((lane >> 4) & 1) * 8) * 36 + ((lane >> 3) & 1) * 4;

    float acc[8][4] = {};

    gemm_core(sm, acc,
              Xh + (size_t)m0 * 512,
              W + ((size_t)h * 192 + sec * 64) * 512,
              tid, aoff, boff);

    const int r = wid * 16 + g;
    const int grow = m0 + r;

    if (sec == 0) {
        // Q: single fp16, pre-scaled 0.125
        #pragma unroll
        for (int nb = 0; nb < 8; nb++) {
            int col = nb * 8 + 2 * t;
            float b0 = qb[h * DK + col], b1 = qb[h * DK + col + 1];
            size_t base = ((size_t)h * NN + grow) * QKS + nb * 4 + t;
            oQh[base]           = pack2h((acc[nb][0] + b0) * 0.125f, (acc[nb][1] + b1) * 0.125f);
            oQh[base + 8 * QKS] = pack2h((acc[nb][2] + b0) * 0.125f, (acc[nb][3] + b1) * 0.125f);
        }
    } else if (sec == 1) {
        // K: single fp16
        #pragma unroll
        for (int nb = 0; nb < 8; nb++) {
            int col = nb * 8 + 2 * t;
            float b0 = kb[h * DK + col], b1 = kb[h * DK + col + 1];
            size_t base = ((size_t)h * NN + grow) * QKS + nb * 4 + t;
            oKh[base]           = pack2h(acc[nb][0] + b0, acc[nb][1] + b1);
            oKh[base + 8 * QKS] = pack2h(acc[nb][2] + b0, acc[nb][3] + b1);
        }
    } else {
        // V: fp16 transpose via smem ([64 dk][132 fp16] = stride 66 u32)
        uint16_t* Vs16 = (uint16_t*)sm;
        #pragma unroll
        for (int nb = 0; nb < 8; nb++) {
            int col = nb * 8 + 2 * t;
            float b0 = vb[h * DK + col], b1 = vb[h * DK + col + 1];
            Vs16[(col)     * 132 + r]     = f16bits(acc[nb][0] + b0);
            Vs16[(col + 1) * 132 + r]     = f16bits(acc[nb][1] + b1);
            Vs16[(col)     * 132 + r + 8] = f16bits(acc[nb][2] + b0);
            Vs16[(col + 1) * 132 + r + 8] = f16bits(acc[nb][3] + b1);
        }
        __syncthreads();
        #pragma unroll
        for (int i = 0; i < 16; i++) {
            int idx = tid + i * 256;
            int dk = idx >> 6, cc = idx & 63;
            oVt[((size_t)h * DK + dk) * (NN / 2) + m0 / 2 + cc] = sm[dk * 66 + cc];
        }
    }
}

// ---------------------------------------------------------------------------
// Out projection + bias + residual: CTA = (row-tile, 64-col tile). 1-term.
// ---------------------------------------------------------------------------
__global__ void __launch_bounds__(256, 3) outproj_kernel(const uint32_t* __restrict__ Ag,
                                                         const uint32_t* __restrict__ Bg,
                                                         const float* __restrict__ x,
                                                         const float* __restrict__ ob,
                                                         float* __restrict__ out)
{
    extern __shared__ uint32_t sm[];
    const int m0 = blockIdx.x * 128;
    const int c0 = blockIdx.y * 64;
    const int tid = threadIdx.x;
    const int wid = tid >> 5, lane = tid & 31, g = lane >> 2, t = lane & 3;
    const int lrow = lane & 7;
    const int aoff = (wid * 16 + lrow + ((lane >> 3) & 1) * 8) * 36 + (lane >> 4) * 4;
    const int boff = (lrow + ((lane >> 4) & 1) * 8) * 36 + ((lane >> 3) & 1) * 4;

    float acc[8][4] = {};

    gemm_core(sm, acc,
              Ag + (size_t)m0 * 512,
              Bg + (size_t)c0 * 512,
              tid, aoff, boff);

    const int r0 = m0 + wid * 16 + g;
    #pragma unroll
    for (int nb = 0; nb < 8; nb++) {
        int col = c0 + nb * 8 + 2 * t;
        float b0 = ob[col], b1 = ob[col + 1];
        const float* xr0 = &x[(size_t)r0 * DM + col];
        const float* xr1 = &x[(size_t)(r0 + 8) * DM + col];
        float2 v0 = make_float2(acc[nb][0] + b0 + xr0[0], acc[nb][1] + b1 + xr0[1]);
        float2 v1 = make_float2(acc[nb][2] + b0 + xr1[0], acc[nb][3] + b1 + xr1[1]);
        *(float2*)&out[(size_t)r0 * DM + col]       = v0;
        *(float2*)&out[(size_t)(r0 + 8) * DM + col] = v1;
    }
}

// ---------------------------------------------------------------------------
// Flash attention: fp16 QK (single-term Q) + fp16 PV.
// buf = Kh[64][36] + Vt[64][36] = 4608 u32 per stage.
// ---------------------------------------------------------------------------
#define ATTN_BUF_U32 (2 * 64 * 36)
#define ATTN_SMEM_BYTES (2 * ATTN_BUF_U32 * 4)

__device__ __forceinline__ void attn_stage(uint32_t* dst, const uint32_t* Kh,
                                           const uint32_t* Vt,
                                           int h, int t0, int tid)
{
    const uint32_t* sKh = Kh + ((size_t)h * NN + t0) * QKS;
    const uint32_t* sVt = Vt + (size_t)h * DK * (NN / 2) + t0 / 2;
    for (int idx = tid; idx < 1088; idx += 256) {
        if (idx < 576) {
            CPA16(dst + idx * 4, sKh + idx * 4);
        } else {
            int j = idx - 576;
            int dk = j >> 3, c = (j & 7) * 4;
            CPA16(dst + 2304 + dk * 36 + c, sVt + (size_t)dk * (NN / 2) + c);
        }
    }
}

__global__ void __launch_bounds__(256, 2) attn_kernel(const uint32_t* __restrict__ Qh,
                                                      const uint32_t* __restrict__ Kh,
                                                      const uint32_t* __restrict__ Vt,
                                                      uint32_t* __restrict__ Ch)
{
    extern __shared__ uint32_t sm[];
    const int h  = blockIdx.y;
    const int q0 = blockIdx.x * 128;
    const int tid = threadIdx.x;
    const int wid = tid >> 5, lane = tid & 31, g = lane >> 2, t = lane & 3;
    const int lrow = lane & 7;
    const int boff = (lrow + ((lane >> 4) & 1) * 8) * 36 + ((lane >> 3) & 1) * 4;

    attn_stage(sm, Kh, Vt, h, 0, tid);
    CP_COMMIT();

    uint32_t ah[4][4];
    {
        const uint32_t* qh = Qh + ((size_t)h * NN + q0 + wid * 16 + g) * QKS;
        #pragma unroll
        for (int ks = 0; ks < 4; ks++) {
            ah[ks][0] = qh[ks * 8 + t];       ah[ks][1] = qh[8 * QKS + ks * 8 + t];
            ah[ks][2] = qh[ks * 8 + t + 4];   ah[ks][3] = qh[8 * QKS + ks * 8 + t + 4];
        }
    }

    float o[8][4] = {};
    float m0 = -1e30f, m1 = -1e30f, l0 = 0.f, l1 = 0.f;

    for (int tt = 0; tt < NN / 64; tt++) {
        uint32_t* buf = sm + (tt & 1) * ATTN_BUF_U32;
        if (tt + 1 < NN / 64) {
            attn_stage(sm + ((tt + 1) & 1) * ATTN_BUF_U32, Kh, Vt, h, (tt + 1) * 64, tid);
            CP_COMMIT();
            CP_WAIT(1);
        } else {
            CP_WAIT(0);
        }
        __syncthreads();

        const uint32_t* kh = buf;
        const uint32_t* vs = buf + 2304;

        float s[8][4] = {};
        #pragma unroll
        for (int ks = 0; ks < 4; ks++) {
            #pragma unroll
            for (int nbp = 0; nbp < 4; nbp++) {
                uint32_t b[4];
                ldsm_x4(b, kh + boff + nbp * 576 + ks * 8);
                mma_f16(s[2 * nbp],     ah[ks], b);
                mma_f16(s[2 * nbp + 1], ah[ks], b + 2);
            }
        }

        float mx0 = -1e30f, mx1 = -1e30f;
        #pragma unroll
        for (int nb = 0; nb < 8; nb++) {
            mx0 = fmaxf(mx0, fmaxf(s[nb][0], s[nb][1]));
            mx1 = fmaxf(mx1, fmaxf(s[nb][2], s[nb][3]));
        }
        mx0 = fmaxf(mx0, __shfl_xor_sync(0xffffffffu, mx0, 1));
        mx0 = fmaxf(mx0, __shfl_xor_sync(0xffffffffu, mx0, 2));
        mx1 = fmaxf(mx1, __shfl_xor_sync(0xffffffffu, mx1, 1));
        mx1 = fmaxf(mx1, __shfl_xor_sync(0xffffffffu, mx1, 2));

        float nm0 = fmaxf(m0, mx0), nm1 = fmaxf(m1, mx1);
        float sc0 = __expf(m0 - nm0), sc1 = __expf(m1 - nm1);
        float sum0 = 0.f, sum1 = 0.f;
        #pragma unroll
        for (int nb = 0; nb < 8; nb++) {
            s[nb][0] = __expf(s[nb][0] - nm0);
            s[nb][1] = __expf(s[nb][1] - nm0);
            s[nb][2] = __expf(s[nb][2] - nm1);
            s[nb][3] = __expf(s[nb][3] - nm1);
            sum0 += s[nb][0] + s[nb][1];
            sum1 += s[nb][2] + s[nb][3];
        }
        sum0 += __shfl_xor_sync(0xffffffffu, sum0, 1);
        sum0 += __shfl_xor_sync(0xffffffffu, sum0, 2);
        sum1 += __shfl_xor_sync(0xffffffffu, sum1, 1);
        sum1 += __shfl_xor_sync(0xffffffffu, sum1, 2);
        l0 = l0 * sc0 + sum0;  m0 = nm0;
        l1 = l1 * sc1 + sum1;  m1 = nm1;
        #pragma unroll
        for (int nb = 0; nb < 8; nb++) {
            o[nb][0] *= sc0; o[nb][1] *= sc0;
            o[nb][2] *= sc1; o[nb][3] *= sc1;
        }

        // O += P V (fp16)
        #pragma unroll
        for (int kp = 0; kp < 4; kp++) {
            uint32_t ap[4];
            ap[0] = pack2h(s[2 * kp][0],     s[2 * kp][1]);
            ap[1] = pack2h(s[2 * kp][2],     s[2 * kp][3]);
            ap[2] = pack2h(s[2 * kp + 1][0], s[2 * kp + 1][1]);
            ap[3] = pack2h(s[2 * kp + 1][2], s[2 * kp + 1][3]);
            #pragma unroll
            for (int nbp = 0; nbp < 4; nbp++) {
                uint32_t b[4];
                ldsm_x4(b, vs + boff + nbp * 576 + kp * 8);
                mma_f16(o[2 * nbp],     ap, b);
                mma_f16(o[2 * nbp + 1], ap, b + 2);
            }
        }
        __syncthreads();
    }

    // epilogue: write concat as single fp16 pairs
    const float inv0 = 1.0f / l0, inv1 = 1.0f / l1;
    const int r0 = q0 + wid * 16 + g;
    #pragma unroll
    for (int nb = 0; nb < 8; nb++) {
        int cpi = h * 32 + nb * 4 + t;
        Ch[(size_t)r0 * 512 + cpi]       = pack2h(o[nb][0] * inv0, o[nb][1] * inv0);
        Ch[(size_t)(r0 + 8) * 512 + cpi] = pack2h(o[nb][2] * inv1, o[nb][3] * inv1);
    }
}

// ---------------------------------------------------------------------------
// LayerNorm, one block per row
// ---------------------------------------------------------------------------
__global__ void __launch_bounds__(256) ln_kernel(const float* __restrict__ pre,
                                                 const float* __restrict__ alpha,
                                                 const float* __restrict__ beta,
                                                 float* __restrict__ out)
{
    const int row = blockIdx.x;
    const int tid = threadIdx.x;
    const float4 v = ((const float4*)(pre + (size_t)row * DM))[tid];

    float sum = v.x + v.y + v.z + v.w;
    float sq  = v.x * v.x + v.y * v.y + v.z * v.z + v.w * v.w;

    #pragma unroll
    for (int d = 16; d >= 1; d >>= 1) {
        sum += __shfl_xor_sync(0xffffffffu, sum, d);
        sq  += __shfl_xor_sync(0xffffffffu, sq,  d);
    }

    __shared__ float ssum[8], ssq[8];
    __shared__ float s_mu, s_rstd;
    int warp = tid >> 5, lane = tid & 31;
    if (lane == 0) { ssum[warp] = sum; ssq[warp] = sq; }
    __syncthreads();
    if (tid == 0) {
        float ts = 0.f, tq = 0.f;
        #pragma unroll
        for (int i = 0; i < 8; i++) { ts += ssum[i]; tq += ssq[i]; }
        float mu  = ts * (1.0f / DM);
        float var = tq * (1.0f / DM) - mu * mu;
        s_mu = mu;
        s_rstd = rsqrtf(var + LN_EPS);
    }
    __syncthreads();

    const float mu = s_mu, rstd = s_rstd;
    const float4 a4 = ((const float4*)alpha)[tid];
    const float4 b4 = ((const float4*)beta)[tid];
    float4 r;
    r.x = a4.x * (v.x - mu) * rstd + b4.x;
    r.y = a4.y * (v.y - mu) * rstd + b4.y;
    r.z = a4.z * (v.z - mu) * rstd + b4.z;
    r.w = a4.w * (v.w - mu) * rstd + b4.w;
    ((float4*)(out + (size_t)row * DM))[tid] = r;
}

// ---------------------------------------------------------------------------
extern "C" void kernel_launch(void* const* d_in, const int* in_sizes, int n_in,
                              void* d_out, int out_size)
{
    const float* x     = (const float*)d_in[0];
    const float* wq    = (const float*)d_in[1];
    const float* qb    = (const float*)d_in[2];
    const float* wk    = (const float*)d_in[3];
    const float* kb    = (const float*)d_in[4];
    const float* wv    = (const float*)d_in[5];
    const float* vb    = (const float*)d_in[6];
    const float* wo    = (const float*)d_in[7];
    const float* ob    = (const float*)d_in[8];
    const float* alpha = (const float*)d_in[9];
    const float* beta  = (const float*)d_in[10];
    float* out = (float*)d_out;

    uint32_t *Xh, *Wq, *Wo;
    uint32_t *Qh, *Kh, *Vt, *Ch;
    float *pre;
    cudaGetSymbolAddress((void**)&Xh,  g_Xh);
    cudaGetSymbolAddress((void**)&Wq,  g_Wq);
    cudaGetSymbolAddress((void**)&Wo,  g_Wo);
    cudaGetSymbolAddress((void**)&Qh,  g_Qh);
    cudaGetSymbolAddress((void**)&Kh,  g_Kh);
    cudaGetSymbolAddress((void**)&Vt,  g_Vt);
    cudaGetSymbolAddress((void**)&Ch,  g_Ch);
    cudaGetSymbolAddress((void**)&pre, g_pre);

    cudaFuncSetAttribute(qkv_kernel,
                         cudaFuncAttributeMaxDynamicSharedMemorySize, G_SMEM);
    cudaFuncSetAttribute(outproj_kernel,
                         cudaFuncAttributeMaxDynamicSharedMemorySize, G_SMEM);
    cudaFuncSetAttribute(attn_kernel,
                         cudaFuncAttributeMaxDynamicSharedMemorySize, ATTN_SMEM_BYTES);

    // conversions
    conv_x_kernel<<<NN, 256>>>(x, Xh);
    conv_wqkv_kernel<<<dim3(16, 1, 48), 256>>>(wq, wk, wv, Wq);
    conv_wo_kernel<<<dim3(16, 16, 1), 256>>>(wo, Wo);

    qkv_kernel<<<dim3(NN / 128, NH, 3), 256, G_SMEM>>>(Xh, Wq,
                                                       qb, kb, vb,
                                                       Qh, Kh, Vt);

    attn_kernel<<<dim3(NN / 128, NH), 256, ATTN_SMEM_BYTES>>>(Qh, Kh, Vt, Ch);

    outproj_kernel<<<dim3(NN / 128, DM / 64), 256, G_SMEM>>>(Ch, Wo,
                                                             x, ob, pre);

    ln_kernel<<<NN, 256>>>(pre, alpha, beta, out);
}